// round 2
// baseline (speedup 1.0000x reference)
#include <cuda_runtime.h>

// ---------------- static scratch (no allocations allowed) ----------------
#define NMAX 122880
#define EMAX 983040

__device__ float g_dinv[NMAX];
__device__ int   g_deg[NMAX];
__device__ int   g_rowptr[NMAX + 1];
__device__ int   g_cursor[NMAX];
__device__ int   g_csr[EMAX];
__device__ int   g_bsum[256];
__device__ int   g_bsumx[256];
__device__ int   g_is64;              // 1 if edge_index delivered as int64
__device__ float g_bufA[NMAX * 128];  // g1 (scaled h1) / g2
__device__ float g_bufB[NMAX * 128];  // y1 / y2

// ---------------- dtype detection for edge_index ----------------
// If int64 (little-endian, values < 2^31), odd 32-bit words are all zero.
// If int32, odd words are random node ids -> flag cleared.
__global__ void k_detect(const int* __restrict__ w, int nwords) {
    int i = blockIdx.x * blockDim.x + threadIdx.x;
    if (i < nwords && (i & 1) && w[i] != 0) g_is64 = 0;
}

// ---------------- degree / dinv ----------------
__global__ void k_zero_deg(int n) {
    int i = blockIdx.x * blockDim.x + threadIdx.x;
    if (i < n) g_deg[i] = 0;
    if (i == 0) g_is64 = 1;
}

__device__ __forceinline__ int load_idx(const int* w, long long pos) {
    // pos = logical element index into the int array [src(E), dst(E)]
    return g_is64 ? w[2 * pos] : w[(int)pos];
}

__global__ void k_count(const int* __restrict__ w, int E, int n) {
    int e = blockIdx.x * blockDim.x + threadIdx.x;
    if (e < E) {
        int d = load_idx(w, (long long)E + e);
        d = min(max(d, 0), n - 1);
        atomicAdd(&g_deg[d], 1);
    }
}

__global__ void k_dinv(int n) {
    int i = blockIdx.x * blockDim.x + threadIdx.x;
    if (i < n) g_dinv[i] = rsqrtf((float)(g_deg[i] + 1));  // +1 self loop
}

// ---------------- exclusive scan of g_deg -> g_rowptr ----------------
__global__ void k_scan1(int n) {
    __shared__ int sh[1024];
    int gid = blockIdx.x * 1024 + threadIdx.x;
    int v = (gid < n) ? g_deg[gid] : 0;
    sh[threadIdx.x] = v;
    __syncthreads();
    for (int off = 1; off < 1024; off <<= 1) {
        int t = (threadIdx.x >= off) ? sh[threadIdx.x - off] : 0;
        __syncthreads();
        sh[threadIdx.x] += t;
        __syncthreads();
    }
    if (gid < n) g_rowptr[gid] = sh[threadIdx.x] - v;  // exclusive
    if (threadIdx.x == 1023) g_bsum[blockIdx.x] = sh[1023];
}

__global__ void k_scan2(int nb) {  // 1 block, 1024 threads
    __shared__ int sh[1024];
    int v = (threadIdx.x < nb) ? g_bsum[threadIdx.x] : 0;
    sh[threadIdx.x] = v;
    __syncthreads();
    for (int off = 1; off < 1024; off <<= 1) {
        int t = (threadIdx.x >= off) ? sh[threadIdx.x - off] : 0;
        __syncthreads();
        sh[threadIdx.x] += t;
        __syncthreads();
    }
    if (threadIdx.x < nb) g_bsumx[threadIdx.x] = sh[threadIdx.x] - v;
}

__global__ void k_scan3(int n, int E) {
    int gid = blockIdx.x * 1024 + threadIdx.x;
    if (gid < n) {
        int r = g_rowptr[gid] + g_bsumx[blockIdx.x];
        g_rowptr[gid] = r;
        g_cursor[gid] = r;
    }
    if (gid == 0) g_rowptr[n] = E;
}

__global__ void k_fill(const int* __restrict__ w, int E, int n) {
    int e = blockIdx.x * blockDim.x + threadIdx.x;
    if (e < E) {
        int d = load_idx(w, (long long)E + e);
        int s = load_idx(w, e);
        d = min(max(d, 0), n - 1);
        s = min(max(s, 0), n - 1);
        int slot = atomicAdd(&g_cursor[d], 1);
        g_csr[min(slot, EMAX - 1)] = s;
    }
}

// ---------------- GEMM1: bufA = (x @ W1) * dinv,  K=64, N=128 ----------------
__global__ __launch_bounds__(256) void k_gemm1(const float* __restrict__ x,
                                               const float* __restrict__ W1) {
    __shared__ float Xs[64 * 64];    // 16 KB
    __shared__ float Ws[64 * 128];   // 32 KB
    int tid = threadIdx.x;
    int r0 = blockIdx.x * 64;

    const float4* W4 = (const float4*)W1;
    float4* Ws4 = (float4*)Ws;
    for (int i = tid; i < 64 * 128 / 4; i += 256) Ws4[i] = W4[i];
    const float4* X4 = (const float4*)(x + (long long)r0 * 64);
    float4* Xs4 = (float4*)Xs;
    for (int i = tid; i < 64 * 64 / 4; i += 256) Xs4[i] = X4[i];
    __syncthreads();

    int tx = tid & 31;   // cols group: tx*4 .. tx*4+3
    int ty = tid >> 5;   // node group: ty*8 .. ty*8+7
    float acc[8][4];
#pragma unroll
    for (int i = 0; i < 8; i++)
#pragma unroll
        for (int j = 0; j < 4; j++) acc[i][j] = 0.f;

    for (int k = 0; k < 64; k++) {
        float4 wv = *(const float4*)&Ws[k * 128 + tx * 4];
#pragma unroll
        for (int nn = 0; nn < 8; nn++) {
            float xv = Xs[(ty * 8 + nn) * 64 + k];
            acc[nn][0] += xv * wv.x;
            acc[nn][1] += xv * wv.y;
            acc[nn][2] += xv * wv.z;
            acc[nn][3] += xv * wv.w;
        }
    }
#pragma unroll
    for (int nn = 0; nn < 8; nn++) {
        int node = r0 + ty * 8 + nn;
        float di = g_dinv[node];
        float4 o = make_float4(acc[nn][0] * di, acc[nn][1] * di,
                               acc[nn][2] * di, acc[nn][3] * di);
        *(float4*)&g_bufA[(long long)node * 128 + tx * 4] = o;
    }
}

// ---------------- gather layer 1: bufB = relu(dinv*(self+sum) + b1), width 128 ----
__global__ void k_gather128(const float* __restrict__ b1, int n) {
    int w = (blockIdx.x * blockDim.x + threadIdx.x) >> 5;
    int lane = threadIdx.x & 31;
    if (w >= n) return;
    int c = lane * 4;
    float4 acc = *(const float4*)&g_bufA[(long long)w * 128 + c];  // self loop
    int e0 = g_rowptr[w], e1 = g_rowptr[w + 1];
    for (int e = e0; e < e1; e++) {
        int s = g_csr[e];
        float4 v = *(const float4*)&g_bufA[(long long)s * 128 + c];
        acc.x += v.x; acc.y += v.y; acc.z += v.z; acc.w += v.w;
    }
    float di = g_dinv[w];
    float4 bb = *(const float4*)&b1[c];
    float4 o = make_float4(fmaxf(di * acc.x + bb.x, 0.f),
                           fmaxf(di * acc.y + bb.y, 0.f),
                           fmaxf(di * acc.z + bb.z, 0.f),
                           fmaxf(di * acc.w + bb.w, 0.f));
    *(float4*)&g_bufB[(long long)w * 128 + c] = o;
}

// ---------------- GEMM2: bufA = (bufB @ W2) * dinv,  K=128, N=64 ----------------
__global__ __launch_bounds__(256) void k_gemm2(const float* __restrict__ W2) {
    __shared__ float Xs[32 * 128];   // 16 KB (32 nodes)
    __shared__ float Ws[128 * 64];   // 32 KB
    int tid = threadIdx.x;
    int r0 = blockIdx.x * 32;

    const float4* W4 = (const float4*)W2;
    float4* Ws4 = (float4*)Ws;
    for (int i = tid; i < 128 * 64 / 4; i += 256) Ws4[i] = W4[i];
    const float4* X4 = (const float4*)(g_bufB + (long long)r0 * 128);
    float4* Xs4 = (float4*)Xs;
    for (int i = tid; i < 32 * 128 / 4; i += 256) Xs4[i] = X4[i];
    __syncthreads();

    int tx = tid & 15;   // cols tx*4
    int ty = tid >> 4;   // nodes ty*2 .. +1
    float acc[2][4];
#pragma unroll
    for (int i = 0; i < 2; i++)
#pragma unroll
        for (int j = 0; j < 4; j++) acc[i][j] = 0.f;

    for (int k = 0; k < 128; k++) {
        float4 wv = *(const float4*)&Ws[k * 64 + tx * 4];
#pragma unroll
        for (int nn = 0; nn < 2; nn++) {
            float xv = Xs[(ty * 2 + nn) * 128 + k];
            acc[nn][0] += xv * wv.x;
            acc[nn][1] += xv * wv.y;
            acc[nn][2] += xv * wv.z;
            acc[nn][3] += xv * wv.w;
        }
    }
#pragma unroll
    for (int nn = 0; nn < 2; nn++) {
        int node = r0 + ty * 2 + nn;
        float di = g_dinv[node];
        float4 o = make_float4(acc[nn][0] * di, acc[nn][1] * di,
                               acc[nn][2] * di, acc[nn][3] * di);
        *(float4*)&g_bufA[(long long)node * 64 + tx * 4] = o;
    }
}

// ---------------- gather layer 2: bufB = relu(dinv*(self+sum) + b2), width 64 ----
__global__ void k_gather64(const float* __restrict__ b2, int n) {
    int w = (blockIdx.x * blockDim.x + threadIdx.x) >> 5;
    int lane = threadIdx.x & 31;
    if (w >= n) return;
    int c = lane * 2;
    float2 acc = *(const float2*)&g_bufA[(long long)w * 64 + c];  // self loop
    int e0 = g_rowptr[w], e1 = g_rowptr[w + 1];
    for (int e = e0; e < e1; e++) {
        int s = g_csr[e];
        float2 v = *(const float2*)&g_bufA[(long long)s * 64 + c];
        acc.x += v.x; acc.y += v.y;
    }
    float di = g_dinv[w];
    float2 bb = *(const float2*)&b2[c];
    float2 o = make_float2(fmaxf(di * acc.x + bb.x, 0.f),
                           fmaxf(di * acc.y + bb.y, 0.f));
    *(float2*)&g_bufB[(long long)w * 64 + c] = o;
}

// ---------------- FC: out[M,N] = bufB[M,K] @ Wfc[K,N] + bfc ----------------
// tile 128x128, 256 threads, 8x8 micro-tile, k-step 8
__global__ __launch_bounds__(256) void k_fc(const float* __restrict__ B,
                                            const float* __restrict__ bias,
                                            float* __restrict__ C,
                                            int M, int N, int K) {
    __shared__ float As[8][132];
    __shared__ float Bs[8][128];
    const float* A = g_bufB;  // [M, K] contiguous

    int tid = threadIdx.x;
    int m0 = blockIdx.y * 128;
    int n0 = blockIdx.x * 128;
    int tx = tid & 15;
    int ty = tid >> 4;

    float acc[8][8];
#pragma unroll
    for (int i = 0; i < 8; i++)
#pragma unroll
        for (int j = 0; j < 8; j++) acc[i][j] = 0.f;

    int la_m = tid >> 3;  // 0..31
    int la_k = tid & 7;   // 0..7
    int lb_k = tid >> 5;  // 0..7
    int lb_n = tid & 31;  // 0..31

    for (int k0 = 0; k0 < K; k0 += 8) {
        __syncthreads();
#pragma unroll
        for (int q = 0; q < 4; q++) {
            int m = la_m + q * 32;
            As[la_k][m] = A[(long long)(m0 + m) * K + k0 + la_k];
        }
#pragma unroll
        for (int q = 0; q < 4; q++) {
            int nn = lb_n + q * 32;
            int gn = n0 + nn;
            Bs[lb_k][nn] = (gn < N) ? B[(long long)(k0 + lb_k) * N + gn] : 0.f;
        }
        __syncthreads();
#pragma unroll
        for (int kk = 0; kk < 8; kk++) {
            float a[8], b[8];
            *(float4*)(a)     = *(const float4*)&As[kk][ty * 8];
            *(float4*)(a + 4) = *(const float4*)&As[kk][ty * 8 + 4];
            *(float4*)(b)     = *(const float4*)&Bs[kk][tx * 8];
            *(float4*)(b + 4) = *(const float4*)&Bs[kk][tx * 8 + 4];
#pragma unroll
            for (int i = 0; i < 8; i++)
#pragma unroll
                for (int j = 0; j < 8; j++) acc[i][j] += a[i] * b[j];
        }
    }

#pragma unroll
    for (int i = 0; i < 8; i++) {
        int m = m0 + ty * 8 + i;
#pragma unroll
        for (int j = 0; j < 8; j++) {
            int nn = n0 + tx * 8 + j;
            if (nn < N) C[(long long)m * N + nn] = acc[i][j] + bias[nn];
        }
    }
}

// ---------------- launch ----------------
extern "C" void kernel_launch(void* const* d_in, const int* in_sizes, int n_in,
                              void* d_out, int out_size) {
    const float* x   = (const float*)d_in[0];
    const int*   ei  = (const int*)d_in[1];   // int32 words; may alias int64 data
    const float* W1  = (const float*)d_in[2];
    const float* b1  = (const float*)d_in[3];
    const float* W2  = (const float*)d_in[4];
    const float* b2  = (const float*)d_in[5];
    const float* Wfc = (const float*)d_in[6];
    const float* bfc = (const float*)d_in[7];
    float* out = (float*)d_out;

    int n = in_sizes[0] / 64;     // 122880
    int E = in_sizes[1] / 2;      // 983040
    int M = out_size / 1728;      // 4096
    int Nfc = 1728, Kfc = 1920;

    // graph structure (recomputed every call; deterministic)
    k_zero_deg<<<(n + 255) / 256, 256>>>(n);
    int det_words = 4096;          // < 2E under both dtype interpretations
    k_detect<<<(det_words + 255) / 256, 256>>>(ei, det_words);
    k_count<<<(E + 255) / 256, 256>>>(ei, E, n);
    k_dinv<<<(n + 255) / 256, 256>>>(n);
    int nb = (n + 1023) / 1024;
    k_scan1<<<nb, 1024>>>(n);
    k_scan2<<<1, 1024>>>(nb);
    k_scan3<<<nb, 1024>>>(n, E);
    k_fill<<<(E + 255) / 256, 256>>>(ei, E, n);

    // layer 1
    k_gemm1<<<n / 64, 256>>>(x, W1);
    k_gather128<<<(n * 32 + 255) / 256, 256>>>(b1, n);
    // layer 2
    k_gemm2<<<n / 32, 256>>>(W2);
    k_gather64<<<(n * 32 + 255) / 256, 256>>>(b2, n);
    // FC head
    dim3 g((Nfc + 127) / 128, M / 128);
    k_fc<<<g, 256>>>(Wfc, bfc, out, M, Nfc, Kfc);
}

// round 3
// speedup vs baseline: 1.7252x; 1.7252x over previous
#include <cuda_runtime.h>

// ---------------- static scratch (no allocations allowed) ----------------
#define NMAX 122880
#define EMAX 983040

__device__ float g_dinv[NMAX];
__device__ int   g_deg[NMAX];
__device__ int   g_rowptr[NMAX + 1];
__device__ int   g_cursor[NMAX];
__device__ int   g_csr[EMAX];
__device__ int   g_bsum[256];
__device__ int   g_bsumx[256];
__device__ int   g_is64;              // 1 if edge_index delivered as int64
__device__ float g_bufA[NMAX * 128];  // g1 (scaled h1) / g2
__device__ float g_bufB[NMAX * 128];  // y1 / y2

// ---------------- dtype detection for edge_index ----------------
__global__ void k_detect(const int* __restrict__ w, int nwords) {
    int i = blockIdx.x * blockDim.x + threadIdx.x;
    if (i < nwords && (i & 1) && w[i] != 0) g_is64 = 0;
}

// ---------------- degree / dinv ----------------
__global__ void k_zero_deg(int n) {
    int i = blockIdx.x * blockDim.x + threadIdx.x;
    if (i < n) g_deg[i] = 0;
    if (i == 0) g_is64 = 1;
}

__device__ __forceinline__ int load_idx(const int* w, long long pos) {
    return g_is64 ? w[2 * pos] : w[(int)pos];
}

__global__ void k_count(const int* __restrict__ w, int E, int n) {
    int e = blockIdx.x * blockDim.x + threadIdx.x;
    if (e < E) {
        int d = load_idx(w, (long long)E + e);
        d = min(max(d, 0), n - 1);
        atomicAdd(&g_deg[d], 1);
    }
}

__global__ void k_dinv(int n) {
    int i = blockIdx.x * blockDim.x + threadIdx.x;
    if (i < n) g_dinv[i] = rsqrtf((float)(g_deg[i] + 1));
}

// ---------------- exclusive scan of g_deg -> g_rowptr ----------------
__global__ void k_scan1(int n) {
    __shared__ int sh[1024];
    int gid = blockIdx.x * 1024 + threadIdx.x;
    int v = (gid < n) ? g_deg[gid] : 0;
    sh[threadIdx.x] = v;
    __syncthreads();
    for (int off = 1; off < 1024; off <<= 1) {
        int t = (threadIdx.x >= off) ? sh[threadIdx.x - off] : 0;
        __syncthreads();
        sh[threadIdx.x] += t;
        __syncthreads();
    }
    if (gid < n) g_rowptr[gid] = sh[threadIdx.x] - v;
    if (threadIdx.x == 1023) g_bsum[blockIdx.x] = sh[1023];
}

__global__ void k_scan2(int nb) {
    __shared__ int sh[1024];
    int v = (threadIdx.x < nb) ? g_bsum[threadIdx.x] : 0;
    sh[threadIdx.x] = v;
    __syncthreads();
    for (int off = 1; off < 1024; off <<= 1) {
        int t = (threadIdx.x >= off) ? sh[threadIdx.x - off] : 0;
        __syncthreads();
        sh[threadIdx.x] += t;
        __syncthreads();
    }
    if (threadIdx.x < nb) g_bsumx[threadIdx.x] = sh[threadIdx.x] - v;
}

__global__ void k_scan3(int n, int E) {
    int gid = blockIdx.x * 1024 + threadIdx.x;
    if (gid < n) {
        int r = g_rowptr[gid] + g_bsumx[blockIdx.x];
        g_rowptr[gid] = r;
        g_cursor[gid] = r;
    }
    if (gid == 0) g_rowptr[n] = E;
}

__global__ void k_fill(const int* __restrict__ w, int E, int n) {
    int e = blockIdx.x * blockDim.x + threadIdx.x;
    if (e < E) {
        int d = load_idx(w, (long long)E + e);
        int s = load_idx(w, e);
        d = min(max(d, 0), n - 1);
        s = min(max(s, 0), n - 1);
        int slot = atomicAdd(&g_cursor[d], 1);
        g_csr[min(slot, EMAX - 1)] = s;
    }
}

// ---------------- GEMM1: bufA = (x @ W1) * dinv,  K=64, N=128 ----------------
__global__ __launch_bounds__(256) void k_gemm1(const float* __restrict__ x,
                                               const float* __restrict__ W1) {
    __shared__ float Xs[64 * 64];
    __shared__ float Ws[64 * 128];
    int tid = threadIdx.x;
    int r0 = blockIdx.x * 64;

    const float4* W4 = (const float4*)W1;
    float4* Ws4 = (float4*)Ws;
    for (int i = tid; i < 64 * 128 / 4; i += 256) Ws4[i] = W4[i];
    const float4* X4 = (const float4*)(x + (long long)r0 * 64);
    float4* Xs4 = (float4*)Xs;
    for (int i = tid; i < 64 * 64 / 4; i += 256) Xs4[i] = X4[i];
    __syncthreads();

    int tx = tid & 31;
    int ty = tid >> 5;
    float acc[8][4];
#pragma unroll
    for (int i = 0; i < 8; i++)
#pragma unroll
        for (int j = 0; j < 4; j++) acc[i][j] = 0.f;

    for (int k = 0; k < 64; k++) {
        float4 wv = *(const float4*)&Ws[k * 128 + tx * 4];
#pragma unroll
        for (int nn = 0; nn < 8; nn++) {
            float xv = Xs[(ty * 8 + nn) * 64 + k];
            acc[nn][0] += xv * wv.x;
            acc[nn][1] += xv * wv.y;
            acc[nn][2] += xv * wv.z;
            acc[nn][3] += xv * wv.w;
        }
    }
#pragma unroll
    for (int nn = 0; nn < 8; nn++) {
        int node = r0 + ty * 8 + nn;
        float di = g_dinv[node];
        float4 o = make_float4(acc[nn][0] * di, acc[nn][1] * di,
                               acc[nn][2] * di, acc[nn][3] * di);
        *(float4*)&g_bufA[(long long)node * 128 + tx * 4] = o;
    }
}

// ---------------- gather layer 1 ----------------
__global__ void k_gather128(const float* __restrict__ b1, int n) {
    int w = (blockIdx.x * blockDim.x + threadIdx.x) >> 5;
    int lane = threadIdx.x & 31;
    if (w >= n) return;
    int c = lane * 4;
    float4 acc = *(const float4*)&g_bufA[(long long)w * 128 + c];
    int e0 = g_rowptr[w], e1 = g_rowptr[w + 1];
    for (int e = e0; e < e1; e++) {
        int s = g_csr[e];
        float4 v = *(const float4*)&g_bufA[(long long)s * 128 + c];
        acc.x += v.x; acc.y += v.y; acc.z += v.z; acc.w += v.w;
    }
    float di = g_dinv[w];
    float4 bb = *(const float4*)&b1[c];
    float4 o = make_float4(fmaxf(di * acc.x + bb.x, 0.f),
                           fmaxf(di * acc.y + bb.y, 0.f),
                           fmaxf(di * acc.z + bb.z, 0.f),
                           fmaxf(di * acc.w + bb.w, 0.f));
    *(float4*)&g_bufB[(long long)w * 128 + c] = o;
}

// ---------------- GEMM2 ----------------
__global__ __launch_bounds__(256) void k_gemm2(const float* __restrict__ W2) {
    __shared__ float Xs[32 * 128];
    __shared__ float Ws[128 * 64];
    int tid = threadIdx.x;
    int r0 = blockIdx.x * 32;

    const float4* W4 = (const float4*)W2;
    float4* Ws4 = (float4*)Ws;
    for (int i = tid; i < 128 * 64 / 4; i += 256) Ws4[i] = W4[i];
    const float4* X4 = (const float4*)(g_bufB + (long long)r0 * 128);
    float4* Xs4 = (float4*)Xs;
    for (int i = tid; i < 32 * 128 / 4; i += 256) Xs4[i] = X4[i];
    __syncthreads();

    int tx = tid & 15;
    int ty = tid >> 4;
    float acc[2][4];
#pragma unroll
    for (int i = 0; i < 2; i++)
#pragma unroll
        for (int j = 0; j < 4; j++) acc[i][j] = 0.f;

    for (int k = 0; k < 128; k++) {
        float4 wv = *(const float4*)&Ws[k * 64 + tx * 4];
#pragma unroll
        for (int nn = 0; nn < 2; nn++) {
            float xv = Xs[(ty * 2 + nn) * 128 + k];
            acc[nn][0] += xv * wv.x;
            acc[nn][1] += xv * wv.y;
            acc[nn][2] += xv * wv.z;
            acc[nn][3] += xv * wv.w;
        }
    }
#pragma unroll
    for (int nn = 0; nn < 2; nn++) {
        int node = r0 + ty * 2 + nn;
        float di = g_dinv[node];
        float4 o = make_float4(acc[nn][0] * di, acc[nn][1] * di,
                               acc[nn][2] * di, acc[nn][3] * di);
        *(float4*)&g_bufA[(long long)node * 64 + tx * 4] = o;
    }
}

// ---------------- gather layer 2 ----------------
__global__ void k_gather64(const float* __restrict__ b2, int n) {
    int w = (blockIdx.x * blockDim.x + threadIdx.x) >> 5;
    int lane = threadIdx.x & 31;
    if (w >= n) return;
    int c = lane * 2;
    float2 acc = *(const float2*)&g_bufA[(long long)w * 64 + c];
    int e0 = g_rowptr[w], e1 = g_rowptr[w + 1];
    for (int e = e0; e < e1; e++) {
        int s = g_csr[e];
        float2 v = *(const float2*)&g_bufA[(long long)s * 64 + c];
        acc.x += v.x; acc.y += v.y;
    }
    float di = g_dinv[w];
    float2 bb = *(const float2*)&b2[c];
    float2 o = make_float2(fmaxf(di * acc.x + bb.x, 0.f),
                           fmaxf(di * acc.y + bb.y, 0.f));
    *(float2*)&g_bufB[(long long)w * 64 + c] = o;
}

// ---------------- FC via tf32 mma.sync: out = bufB[M,K] @ Wfc[K,N] + bfc ----
// block tile 128x128, 4 warps (2x2), warp tile 64x64, BK=16, double-buffered.
#define FC_BK 16
#define LDA 20     // 16 + 4 pad (words) -> conflict-free frag reads, 16B-aligned rows
#define LDB 136    // 128 + 8 pad

__device__ __forceinline__ float f2tf32(float x) {
    unsigned u;
    asm("cvt.rna.tf32.f32 %0, %1;" : "=r"(u) : "f"(x));
    return __uint_as_float(u);
}

__global__ __launch_bounds__(128) void k_fc_tf32(const float* __restrict__ B,
                                                 const float* __restrict__ bias,
                                                 float* __restrict__ C,
                                                 int M, int N, int K) {
    __shared__ float As[2][128 * LDA];      // [m][k]
    __shared__ float Bs[2][FC_BK * LDB];    // [k][n]
    const float* A = g_bufB;

    int tid = threadIdx.x;
    int m0 = blockIdx.y * 128;
    int n0 = blockIdx.x * 128;

    int w  = tid >> 5;
    int wm = (w >> 1) * 64;   // warp row offset in tile
    int wn = (w & 1) * 64;    // warp col offset in tile
    int lane = tid & 31;
    int g = lane >> 2;        // groupID
    int t = lane & 3;         // threadID_in_group

    // per-thread global load coords
    int a_row = tid;                 // 0..127
    int b_kr  = tid >> 3;            // 0..15
    int b_nc  = (tid & 7) * 16;      // 0,16,..,112

    float c[4][8][4];
#pragma unroll
    for (int i = 0; i < 4; i++)
#pragma unroll
        for (int j = 0; j < 8; j++)
#pragma unroll
            for (int q = 0; q < 4; q++) c[i][j][q] = 0.f;

    int NKT = K / FC_BK;

    // ---- prologue: load tile 0 ----
    {
        const float4* ap = (const float4*)&A[(long long)(m0 + a_row) * K];
#pragma unroll
        for (int q = 0; q < 4; q++) {
            float4 v = ap[q];
            float4 o = make_float4(f2tf32(v.x), f2tf32(v.y), f2tf32(v.z), f2tf32(v.w));
            *(float4*)&As[0][a_row * LDA + q * 4] = o;
        }
#pragma unroll
        for (int q = 0; q < 4; q++) {
            int gn = n0 + b_nc + q * 4;
            float4 v = (gn + 3 < N) ? *(const float4*)&B[(long long)b_kr * N + gn]
                                    : make_float4(0.f, 0.f, 0.f, 0.f);
            float4 o = make_float4(f2tf32(v.x), f2tf32(v.y), f2tf32(v.z), f2tf32(v.w));
            *(float4*)&Bs[0][b_kr * LDB + b_nc + q * 4] = o;
        }
    }
    __syncthreads();

    for (int kt = 0; kt < NKT; kt++) {
        int cur = kt & 1;
        bool hn = (kt + 1) < NKT;
        float4 ra[4], rb[4];
        if (hn) {
            int k0 = (kt + 1) * FC_BK;
            const float4* ap = (const float4*)&A[(long long)(m0 + a_row) * K + k0];
#pragma unroll
            for (int q = 0; q < 4; q++) ra[q] = ap[q];
#pragma unroll
            for (int q = 0; q < 4; q++) {
                int gn = n0 + b_nc + q * 4;
                rb[q] = (gn + 3 < N) ? *(const float4*)&B[(long long)(k0 + b_kr) * N + gn]
                                     : make_float4(0.f, 0.f, 0.f, 0.f);
            }
        }

        // ---- compute on buffer cur ----
        const float* as = As[cur];
        const float* bs = Bs[cur];
#pragma unroll
        for (int ks = 0; ks < 2; ks++) {
            unsigned af[4][4];
#pragma unroll
            for (int i = 0; i < 4; i++) {
                int rb0 = wm + i * 16 + g;
                int col = ks * 8 + t;
                af[i][0] = __float_as_uint(as[rb0 * LDA + col]);
                af[i][1] = __float_as_uint(as[(rb0 + 8) * LDA + col]);
                af[i][2] = __float_as_uint(as[rb0 * LDA + col + 4]);
                af[i][3] = __float_as_uint(as[(rb0 + 8) * LDA + col + 4]);
            }
            unsigned bf[8][2];
#pragma unroll
            for (int j = 0; j < 8; j++) {
                int col = wn + j * 8 + g;
                int row = ks * 8 + t;
                bf[j][0] = __float_as_uint(bs[row * LDB + col]);
                bf[j][1] = __float_as_uint(bs[(row + 4) * LDB + col]);
            }
#pragma unroll
            for (int i = 0; i < 4; i++)
#pragma unroll
                for (int j = 0; j < 8; j++) {
                    asm volatile(
                        "mma.sync.aligned.m16n8k8.row.col.f32.tf32.tf32.f32 "
                        "{%0,%1,%2,%3}, {%4,%5,%6,%7}, {%8,%9}, {%0,%1,%2,%3};"
                        : "+f"(c[i][j][0]), "+f"(c[i][j][1]),
                          "+f"(c[i][j][2]), "+f"(c[i][j][3])
                        : "r"(af[i][0]), "r"(af[i][1]), "r"(af[i][2]), "r"(af[i][3]),
                          "r"(bf[j][0]), "r"(bf[j][1]));
                }
        }

        if (hn) {
            int nxt = (kt + 1) & 1;
#pragma unroll
            for (int q = 0; q < 4; q++) {
                float4 v = ra[q];
                float4 o = make_float4(f2tf32(v.x), f2tf32(v.y), f2tf32(v.z), f2tf32(v.w));
                *(float4*)&As[nxt][a_row * LDA + q * 4] = o;
            }
#pragma unroll
            for (int q = 0; q < 4; q++) {
                float4 v = rb[q];
                float4 o = make_float4(f2tf32(v.x), f2tf32(v.y), f2tf32(v.z), f2tf32(v.w));
                *(float4*)&Bs[nxt][b_kr * LDB + b_nc + q * 4] = o;
            }
        }
        __syncthreads();
    }

    // ---- epilogue: C = acc + bias ----
#pragma unroll
    for (int i = 0; i < 4; i++) {
        int r0 = m0 + wm + i * 16 + g;
#pragma unroll
        for (int j = 0; j < 8; j++) {
            int cb = n0 + wn + j * 8 + 2 * t;
            if (cb < N) {
                float2 bb = *(const float2*)&bias[cb];
                float2 o0 = make_float2(c[i][j][0] + bb.x, c[i][j][1] + bb.y);
                float2 o1 = make_float2(c[i][j][2] + bb.x, c[i][j][3] + bb.y);
                *(float2*)&C[(long long)r0 * N + cb] = o0;
                *(float2*)&C[(long long)(r0 + 8) * N + cb] = o1;
            }
        }
    }
}

// ---------------- launch ----------------
extern "C" void kernel_launch(void* const* d_in, const int* in_sizes, int n_in,
                              void* d_out, int out_size) {
    const float* x   = (const float*)d_in[0];
    const int*   ei  = (const int*)d_in[1];
    const float* W1  = (const float*)d_in[2];
    const float* b1  = (const float*)d_in[3];
    const float* W2  = (const float*)d_in[4];
    const float* b2  = (const float*)d_in[5];
    const float* Wfc = (const float*)d_in[6];
    const float* bfc = (const float*)d_in[7];
    float* out = (float*)d_out;

    int n = in_sizes[0] / 64;     // 122880
    int E = in_sizes[1] / 2;      // 983040
    int M = out_size / 1728;      // 4096
    int Nfc = 1728, Kfc = 1920;

    k_zero_deg<<<(n + 255) / 256, 256>>>(n);
    k_detect<<<16, 256>>>(ei, 4096);
    k_count<<<(E + 255) / 256, 256>>>(ei, E, n);
    k_dinv<<<(n + 255) / 256, 256>>>(n);
    int nb = (n + 1023) / 1024;
    k_scan1<<<nb, 1024>>>(n);
    k_scan2<<<1, 1024>>>(nb);
    k_scan3<<<nb, 1024>>>(n, E);
    k_fill<<<(E + 255) / 256, 256>>>(ei, E, n);

    k_gemm1<<<n / 64, 256>>>(x, W1);
    k_gather128<<<(n * 32 + 255) / 256, 256>>>(b1, n);
    k_gemm2<<<n / 32, 256>>>(W2);
    k_gather64<<<(n * 32 + 255) / 256, 256>>>(b2, n);

    dim3 g((Nfc + 127) / 128, M / 128);
    k_fc_tf32<<<g, 128>>>(Wfc, bfc, out, M, Nfc, Kfc);
}

// round 4
// speedup vs baseline: 1.7434x; 1.0105x over previous
#include <cuda_runtime.h>

// ---------------- static scratch (no allocations allowed) ----------------
#define NMAX 122880
#define EMAX 983040

__device__ float g_dinv[NMAX];
__device__ int   g_deg[NMAX];
__device__ int   g_rowptr[NMAX + 1];
__device__ int   g_cursor[NMAX];
__device__ int   g_csr[EMAX];
__device__ int   g_bsum[256];
__device__ int   g_bsumx[256];
__device__ int   g_is64;              // 1 if edge_index delivered as int64
__device__ float g_bufA[NMAX * 128];  // g1 (scaled h1) / g2
__device__ float g_bufB[NMAX * 128];  // y1 / y2 (tf32-rounded after gather64)
__device__ float g_Wtf[1920 * 1728];  // Wfc pre-rounded to tf32

// ---------------- dtype detection for edge_index ----------------
__global__ void k_detect(const int* __restrict__ w, int nwords) {
    int i = blockIdx.x * blockDim.x + threadIdx.x;
    if (i < nwords && (i & 1) && w[i] != 0) g_is64 = 0;
}

// ---------------- degree / dinv ----------------
__global__ void k_zero_deg(int n) {
    int i = blockIdx.x * blockDim.x + threadIdx.x;
    if (i < n) g_deg[i] = 0;
    if (i == 0) g_is64 = 1;
}

__device__ __forceinline__ int load_idx(const int* w, long long pos) {
    return g_is64 ? w[2 * pos] : w[(int)pos];
}

__global__ void k_count(const int* __restrict__ w, int E, int n) {
    int e = blockIdx.x * blockDim.x + threadIdx.x;
    if (e < E) {
        int d = load_idx(w, (long long)E + e);
        d = min(max(d, 0), n - 1);
        atomicAdd(&g_deg[d], 1);
    }
}

__global__ void k_dinv(int n) {
    int i = blockIdx.x * blockDim.x + threadIdx.x;
    if (i < n) g_dinv[i] = rsqrtf((float)(g_deg[i] + 1));
}

// ---------------- exclusive scan of g_deg -> g_rowptr ----------------
__global__ void k_scan1(int n) {
    __shared__ int sh[1024];
    int gid = blockIdx.x * 1024 + threadIdx.x;
    int v = (gid < n) ? g_deg[gid] : 0;
    sh[threadIdx.x] = v;
    __syncthreads();
    for (int off = 1; off < 1024; off <<= 1) {
        int t = (threadIdx.x >= off) ? sh[threadIdx.x - off] : 0;
        __syncthreads();
        sh[threadIdx.x] += t;
        __syncthreads();
    }
    if (gid < n) g_rowptr[gid] = sh[threadIdx.x] - v;
    if (threadIdx.x == 1023) g_bsum[blockIdx.x] = sh[1023];
}

__global__ void k_scan2(int nb) {
    __shared__ int sh[1024];
    int v = (threadIdx.x < nb) ? g_bsum[threadIdx.x] : 0;
    sh[threadIdx.x] = v;
    __syncthreads();
    for (int off = 1; off < 1024; off <<= 1) {
        int t = (threadIdx.x >= off) ? sh[threadIdx.x - off] : 0;
        __syncthreads();
        sh[threadIdx.x] += t;
        __syncthreads();
    }
    if (threadIdx.x < nb) g_bsumx[threadIdx.x] = sh[threadIdx.x] - v;
}

__global__ void k_scan3(int n, int E) {
    int gid = blockIdx.x * 1024 + threadIdx.x;
    if (gid < n) {
        int r = g_rowptr[gid] + g_bsumx[blockIdx.x];
        g_rowptr[gid] = r;
        g_cursor[gid] = r;
    }
    if (gid == 0) g_rowptr[n] = E;
}

__global__ void k_fill(const int* __restrict__ w, int E, int n) {
    int e = blockIdx.x * blockDim.x + threadIdx.x;
    if (e < E) {
        int d = load_idx(w, (long long)E + e);
        int s = load_idx(w, e);
        d = min(max(d, 0), n - 1);
        s = min(max(s, 0), n - 1);
        int slot = atomicAdd(&g_cursor[d], 1);
        g_csr[min(slot, EMAX - 1)] = s;
    }
}

// ---------------- tf32 helpers ----------------
__device__ __forceinline__ float f2tf32(float x) {
    unsigned u;
    asm("cvt.rna.tf32.f32 %0, %1;" : "=r"(u) : "f"(x));
    return __uint_as_float(u);
}

// pre-round Wfc -> g_Wtf
__global__ void k_cvt_w(const float* __restrict__ W, int total) {
    int i = blockIdx.x * blockDim.x + threadIdx.x;
    if (i * 4 < total) {
        float4 v = *(const float4*)&W[i * 4];
        float4 o = make_float4(f2tf32(v.x), f2tf32(v.y), f2tf32(v.z), f2tf32(v.w));
        *(float4*)&g_Wtf[i * 4] = o;
    }
}

// ---------------- GEMM1: bufA = (x @ W1) * dinv,  K=64, N=128 ----------------
__global__ __launch_bounds__(256) void k_gemm1(const float* __restrict__ x,
                                               const float* __restrict__ W1) {
    __shared__ float Xs[64 * 64];
    __shared__ float Ws[64 * 128];
    int tid = threadIdx.x;
    int r0 = blockIdx.x * 64;

    const float4* W4 = (const float4*)W1;
    float4* Ws4 = (float4*)Ws;
    for (int i = tid; i < 64 * 128 / 4; i += 256) Ws4[i] = W4[i];
    const float4* X4 = (const float4*)(x + (long long)r0 * 64);
    float4* Xs4 = (float4*)Xs;
    for (int i = tid; i < 64 * 64 / 4; i += 256) Xs4[i] = X4[i];
    __syncthreads();

    int tx = tid & 31;
    int ty = tid >> 5;
    float acc[8][4];
#pragma unroll
    for (int i = 0; i < 8; i++)
#pragma unroll
        for (int j = 0; j < 4; j++) acc[i][j] = 0.f;

    for (int k = 0; k < 64; k++) {
        float4 wv = *(const float4*)&Ws[k * 128 + tx * 4];
#pragma unroll
        for (int nn = 0; nn < 8; nn++) {
            float xv = Xs[(ty * 8 + nn) * 64 + k];
            acc[nn][0] += xv * wv.x;
            acc[nn][1] += xv * wv.y;
            acc[nn][2] += xv * wv.z;
            acc[nn][3] += xv * wv.w;
        }
    }
#pragma unroll
    for (int nn = 0; nn < 8; nn++) {
        int node = r0 + ty * 8 + nn;
        float di = g_dinv[node];
        float4 o = make_float4(acc[nn][0] * di, acc[nn][1] * di,
                               acc[nn][2] * di, acc[nn][3] * di);
        *(float4*)&g_bufA[(long long)node * 128 + tx * 4] = o;
    }
}

// ---------------- gather layer 1 ----------------
__global__ void k_gather128(const float* __restrict__ b1, int n) {
    int w = (blockIdx.x * blockDim.x + threadIdx.x) >> 5;
    int lane = threadIdx.x & 31;
    if (w >= n) return;
    int c = lane * 4;
    float4 acc = *(const float4*)&g_bufA[(long long)w * 128 + c];
    int e0 = g_rowptr[w], e1 = g_rowptr[w + 1];
    for (int e = e0; e < e1; e++) {
        int s = g_csr[e];
        float4 v = *(const float4*)&g_bufA[(long long)s * 128 + c];
        acc.x += v.x; acc.y += v.y; acc.z += v.z; acc.w += v.w;
    }
    float di = g_dinv[w];
    float4 bb = *(const float4*)&b1[c];
    float4 o = make_float4(fmaxf(di * acc.x + bb.x, 0.f),
                           fmaxf(di * acc.y + bb.y, 0.f),
                           fmaxf(di * acc.z + bb.z, 0.f),
                           fmaxf(di * acc.w + bb.w, 0.f));
    *(float4*)&g_bufB[(long long)w * 128 + c] = o;
}

// ---------------- GEMM2 ----------------
__global__ __launch_bounds__(256) void k_gemm2(const float* __restrict__ W2) {
    __shared__ float Xs[32 * 128];
    __shared__ float Ws[128 * 64];
    int tid = threadIdx.x;
    int r0 = blockIdx.x * 32;

    const float4* W4 = (const float4*)W2;
    float4* Ws4 = (float4*)Ws;
    for (int i = tid; i < 128 * 64 / 4; i += 256) Ws4[i] = W4[i];
    const float4* X4 = (const float4*)(g_bufB + (long long)r0 * 128);
    float4* Xs4 = (float4*)Xs;
    for (int i = tid; i < 32 * 128 / 4; i += 256) Xs4[i] = X4[i];
    __syncthreads();

    int tx = tid & 15;
    int ty = tid >> 4;
    float acc[2][4];
#pragma unroll
    for (int i = 0; i < 2; i++)
#pragma unroll
        for (int j = 0; j < 4; j++) acc[i][j] = 0.f;

    for (int k = 0; k < 128; k++) {
        float4 wv = *(const float4*)&Ws[k * 64 + tx * 4];
#pragma unroll
        for (int nn = 0; nn < 2; nn++) {
            float xv = Xs[(ty * 2 + nn) * 128 + k];
            acc[nn][0] += xv * wv.x;
            acc[nn][1] += xv * wv.y;
            acc[nn][2] += xv * wv.z;
            acc[nn][3] += xv * wv.w;
        }
    }
#pragma unroll
    for (int nn = 0; nn < 2; nn++) {
        int node = r0 + ty * 2 + nn;
        float di = g_dinv[node];
        float4 o = make_float4(acc[nn][0] * di, acc[nn][1] * di,
                               acc[nn][2] * di, acc[nn][3] * di);
        *(float4*)&g_bufA[(long long)node * 64 + tx * 4] = o;
    }
}

// ---------------- gather layer 2 (writes tf32-rounded, feeds only FC) ----------
__global__ void k_gather64(const float* __restrict__ b2, int n) {
    int w = (blockIdx.x * blockDim.x + threadIdx.x) >> 5;
    int lane = threadIdx.x & 31;
    if (w >= n) return;
    int c = lane * 2;
    float2 acc = *(const float2*)&g_bufA[(long long)w * 64 + c];
    int e0 = g_rowptr[w], e1 = g_rowptr[w + 1];
    for (int e = e0; e < e1; e++) {
        int s = g_csr[e];
        float2 v = *(const float2*)&g_bufA[(long long)s * 64 + c];
        acc.x += v.x; acc.y += v.y;
    }
    float di = g_dinv[w];
    float2 bb = *(const float2*)&b2[c];
    float2 o = make_float2(f2tf32(fmaxf(di * acc.x + bb.x, 0.f)),
                           f2tf32(fmaxf(di * acc.y + bb.y, 0.f)));
    *(float2*)&g_bufB[(long long)w * 64 + c] = o;
}

// ---------------- FC via tf32 mma.sync: out = bufB[M,K] @ g_Wtf[K,N] + bfc ----
// block tile 128x128, 4 warps (2x2), warp tile 64x64, BK=16, double-buffered.
// inputs pre-rounded to tf32 -> no cvt in mainloop.
#define FC_BK 16
#define LDA 20
#define LDB 136

__global__ __launch_bounds__(128) void k_fc_tf32(const float* __restrict__ bias,
                                                 float* __restrict__ C,
                                                 int M, int N, int K) {
    __shared__ float As[2][128 * LDA];      // [m][k]
    __shared__ float Bs[2][FC_BK * LDB];    // [k][n]
    const float* A = g_bufB;
    const float* B = g_Wtf;

    int tid = threadIdx.x;
    int m0 = blockIdx.y * 128;
    int n0 = blockIdx.x * 128;

    int w  = tid >> 5;
    int wm = (w >> 1) * 64;
    int wn = (w & 1) * 64;
    int lane = tid & 31;
    int g = lane >> 2;
    int t = lane & 3;

    int a_row = tid;
    int b_kr  = tid >> 3;
    int b_nc  = (tid & 7) * 16;

    float c[4][8][4];
#pragma unroll
    for (int i = 0; i < 4; i++)
#pragma unroll
        for (int j = 0; j < 8; j++)
#pragma unroll
            for (int q = 0; q < 4; q++) c[i][j][q] = 0.f;

    int NKT = K / FC_BK;

    // ---- prologue: load tile 0 ----
    {
        const float4* ap = (const float4*)&A[(long long)(m0 + a_row) * K];
#pragma unroll
        for (int q = 0; q < 4; q++)
            *(float4*)&As[0][a_row * LDA + q * 4] = ap[q];
#pragma unroll
        for (int q = 0; q < 4; q++) {
            int gn = n0 + b_nc + q * 4;
            float4 v = (gn + 3 < N) ? *(const float4*)&B[(long long)b_kr * N + gn]
                                    : make_float4(0.f, 0.f, 0.f, 0.f);
            *(float4*)&Bs[0][b_kr * LDB + b_nc + q * 4] = v;
        }
    }
    __syncthreads();

    for (int kt = 0; kt < NKT; kt++) {
        int cur = kt & 1;
        bool hn = (kt + 1) < NKT;
        float4 ra[4], rb[4];
        if (hn) {
            int k0 = (kt + 1) * FC_BK;
            const float4* ap = (const float4*)&A[(long long)(m0 + a_row) * K + k0];
#pragma unroll
            for (int q = 0; q < 4; q++) ra[q] = ap[q];
#pragma unroll
            for (int q = 0; q < 4; q++) {
                int gn = n0 + b_nc + q * 4;
                rb[q] = (gn + 3 < N) ? *(const float4*)&B[(long long)(k0 + b_kr) * N + gn]
                                     : make_float4(0.f, 0.f, 0.f, 0.f);
            }
        }

        const float* as = As[cur];
        const float* bs = Bs[cur];
#pragma unroll
        for (int ks = 0; ks < 2; ks++) {
            unsigned af[4][4];
#pragma unroll
            for (int i = 0; i < 4; i++) {
                int rb0 = wm + i * 16 + g;
                int col = ks * 8 + t;
                af[i][0] = __float_as_uint(as[rb0 * LDA + col]);
                af[i][1] = __float_as_uint(as[(rb0 + 8) * LDA + col]);
                af[i][2] = __float_as_uint(as[rb0 * LDA + col + 4]);
                af[i][3] = __float_as_uint(as[(rb0 + 8) * LDA + col + 4]);
            }
            unsigned bf[8][2];
#pragma unroll
            for (int j = 0; j < 8; j++) {
                int col = wn + j * 8 + g;
                int row = ks * 8 + t;
                bf[j][0] = __float_as_uint(bs[row * LDB + col]);
                bf[j][1] = __float_as_uint(bs[(row + 4) * LDB + col]);
            }
#pragma unroll
            for (int i = 0; i < 4; i++)
#pragma unroll
                for (int j = 0; j < 8; j++) {
                    asm volatile(
                        "mma.sync.aligned.m16n8k8.row.col.f32.tf32.tf32.f32 "
                        "{%0,%1,%2,%3}, {%4,%5,%6,%7}, {%8,%9}, {%0,%1,%2,%3};"
                        : "+f"(c[i][j][0]), "+f"(c[i][j][1]),
                          "+f"(c[i][j][2]), "+f"(c[i][j][3])
                        : "r"(af[i][0]), "r"(af[i][1]), "r"(af[i][2]), "r"(af[i][3]),
                          "r"(bf[j][0]), "r"(bf[j][1]));
                }
        }

        if (hn) {
            int nxt = (kt + 1) & 1;
#pragma unroll
            for (int q = 0; q < 4; q++)
                *(float4*)&As[nxt][a_row * LDA + q * 4] = ra[q];
#pragma unroll
            for (int q = 0; q < 4; q++)
                *(float4*)&Bs[nxt][b_kr * LDB + b_nc + q * 4] = rb[q];
        }
        __syncthreads();
    }

    // ---- epilogue ----
#pragma unroll
    for (int i = 0; i < 4; i++) {
        int r0 = m0 + wm + i * 16 + g;
#pragma unroll
        for (int j = 0; j < 8; j++) {
            int cb = n0 + wn + j * 8 + 2 * t;
            if (cb < N) {
                float2 bb = *(const float2*)&bias[cb];
                float2 o0 = make_float2(c[i][j][0] + bb.x, c[i][j][1] + bb.y);
                float2 o1 = make_float2(c[i][j][2] + bb.x, c[i][j][3] + bb.y);
                *(float2*)&C[(long long)r0 * N + cb] = o0;
                *(float2*)&C[(long long)(r0 + 8) * N + cb] = o1;
            }
        }
    }
}

// ---------------- launch ----------------
extern "C" void kernel_launch(void* const* d_in, const int* in_sizes, int n_in,
                              void* d_out, int out_size) {
    const float* x   = (const float*)d_in[0];
    const int*   ei  = (const int*)d_in[1];
    const float* W1  = (const float*)d_in[2];
    const float* b1  = (const float*)d_in[3];
    const float* W2  = (const float*)d_in[4];
    const float* b2  = (const float*)d_in[5];
    const float* Wfc = (const float*)d_in[6];
    const float* bfc = (const float*)d_in[7];
    float* out = (float*)d_out;

    int n = in_sizes[0] / 64;     // 122880
    int E = in_sizes[1] / 2;      // 983040
    int M = out_size / 1728;      // 4096
    int Nfc = 1728, Kfc = 1920;

    k_zero_deg<<<(n + 255) / 256, 256>>>(n);
    k_detect<<<16, 256>>>(ei, 4096);
    k_count<<<(E + 255) / 256, 256>>>(ei, E, n);
    k_dinv<<<(n + 255) / 256, 256>>>(n);
    int nb = (n + 1023) / 1024;
    k_scan1<<<nb, 1024>>>(n);
    k_scan2<<<1, 1024>>>(nb);
    k_scan3<<<nb, 1024>>>(n, E);
    k_fill<<<(E + 255) / 256, 256>>>(ei, E, n);

    // pre-round Wfc to tf32 (overlappable with graph prep / layer work)
    int wtot = Kfc * Nfc;
    k_cvt_w<<<(wtot / 4 + 255) / 256, 256>>>(Wfc, wtot);

    k_gemm1<<<n / 64, 256>>>(x, W1);
    k_gather128<<<(n * 32 + 255) / 256, 256>>>(b1, n);
    k_gemm2<<<n / 32, 256>>>(W2);
    k_gather64<<<(n * 32 + 255) / 256, 256>>>(b2, n);

    dim3 g((Nfc + 127) / 128, M / 128);
    k_fc_tf32<<<g, 128>>>(bfc, out, M, Nfc, Kfc);
}

// round 5
// speedup vs baseline: 2.7779x; 1.5934x over previous
#include <cuda_runtime.h>
#include <cuda_fp16.h>

// ---------------- static scratch (no allocations allowed) ----------------
#define NMAX 122880
#define EMAX 983040

__device__ float g_dinv[NMAX];
__device__ int   g_deg[NMAX];
__device__ int   g_rowptr[NMAX + 1];
__device__ int   g_cursor[NMAX];
__device__ int   g_csr[EMAX];
__device__ int   g_bsum[256];
__device__ int   g_bsumx[256];
__device__ int   g_is64;
__device__ float g_bufA[NMAX * 128];
__device__ float g_bufB[NMAX * 128];
__device__ __half g_bufH[NMAX * 64];            // FC A operand, [4096][1920] halfs
__device__ __half g_Whalf[14 * 960 * 256];      // Wfc blocked: [nblk][kp][128 half2]

// ---------------- dtype detection ----------------
__global__ void k_detect(const int* __restrict__ w, int nwords) {
    int i = blockIdx.x * blockDim.x + threadIdx.x;
    if (i < nwords && (i & 1) && w[i] != 0) g_is64 = 0;
}

__global__ void k_zero_deg(int n) {
    int i = blockIdx.x * blockDim.x + threadIdx.x;
    if (i < n) g_deg[i] = 0;
    if (i == 0) g_is64 = 1;
}

__device__ __forceinline__ int load_idx(const int* w, long long pos) {
    return g_is64 ? w[2 * pos] : w[(int)pos];
}

__global__ void k_count(const int* __restrict__ w, int E, int n) {
    int e = blockIdx.x * blockDim.x + threadIdx.x;
    if (e < E) {
        int d = load_idx(w, (long long)E + e);
        d = min(max(d, 0), n - 1);
        atomicAdd(&g_deg[d], 1);
    }
}

__global__ void k_dinv(int n) {
    int i = blockIdx.x * blockDim.x + threadIdx.x;
    if (i < n) g_dinv[i] = rsqrtf((float)(g_deg[i] + 1));
}

// ---------------- exclusive scan ----------------
__global__ void k_scan1(int n) {
    __shared__ int sh[1024];
    int gid = blockIdx.x * 1024 + threadIdx.x;
    int v = (gid < n) ? g_deg[gid] : 0;
    sh[threadIdx.x] = v;
    __syncthreads();
    for (int off = 1; off < 1024; off <<= 1) {
        int t = (threadIdx.x >= off) ? sh[threadIdx.x - off] : 0;
        __syncthreads();
        sh[threadIdx.x] += t;
        __syncthreads();
    }
    if (gid < n) g_rowptr[gid] = sh[threadIdx.x] - v;
    if (threadIdx.x == 1023) g_bsum[blockIdx.x] = sh[1023];
}

__global__ void k_scan2(int nb) {
    __shared__ int sh[1024];
    int v = (threadIdx.x < nb) ? g_bsum[threadIdx.x] : 0;
    sh[threadIdx.x] = v;
    __syncthreads();
    for (int off = 1; off < 1024; off <<= 1) {
        int t = (threadIdx.x >= off) ? sh[threadIdx.x - off] : 0;
        __syncthreads();
        sh[threadIdx.x] += t;
        __syncthreads();
    }
    if (threadIdx.x < nb) g_bsumx[threadIdx.x] = sh[threadIdx.x] - v;
}

__global__ void k_scan3(int n, int E) {
    int gid = blockIdx.x * 1024 + threadIdx.x;
    if (gid < n) {
        int r = g_rowptr[gid] + g_bsumx[blockIdx.x];
        g_rowptr[gid] = r;
        g_cursor[gid] = r;
    }
    if (gid == 0) g_rowptr[n] = E;
}

__global__ void k_fill(const int* __restrict__ w, int E, int n) {
    int e = blockIdx.x * blockDim.x + threadIdx.x;
    if (e < E) {
        int d = load_idx(w, (long long)E + e);
        int s = load_idx(w, e);
        d = min(max(d, 0), n - 1);
        s = min(max(s, 0), n - 1);
        int slot = atomicAdd(&g_cursor[d], 1);
        g_csr[min(slot, EMAX - 1)] = s;
    }
}

// ---------------- Wfc -> blocked half layout ----------------
// g_Whalf half2 index = bx*(960*128) + kp*128 + n_local ; value {W[2kp][n], W[2kp+1][n]}
__global__ void k_cvt_wh(const float* __restrict__ W, int N) {
    int idx = blockIdx.x * blockDim.x + threadIdx.x;   // 14*960*128
    if (idx >= 14 * 960 * 128) return;
    int n_local = idx & 127;
    int kp = (idx >> 7) % 960;
    int bx = idx / (960 * 128);
    int n = bx * 128 + n_local;
    float lo = 0.f, hi = 0.f;
    if (n < N) {
        lo = W[(long long)(2 * kp) * N + n];
        hi = W[(long long)(2 * kp + 1) * N + n];
    }
    ((__half2*)g_Whalf)[idx] = __floats2half2_rn(lo, hi);
}

// ---------------- GEMM1: bufA = (x @ W1) * dinv ----------------
__global__ __launch_bounds__(256) void k_gemm1(const float* __restrict__ x,
                                               const float* __restrict__ W1) {
    __shared__ float Xs[64 * 64];
    __shared__ float Ws[64 * 128];
    int tid = threadIdx.x;
    int r0 = blockIdx.x * 64;

    const float4* W4 = (const float4*)W1;
    float4* Ws4 = (float4*)Ws;
    for (int i = tid; i < 64 * 128 / 4; i += 256) Ws4[i] = W4[i];
    const float4* X4 = (const float4*)(x + (long long)r0 * 64);
    float4* Xs4 = (float4*)Xs;
    for (int i = tid; i < 64 * 64 / 4; i += 256) Xs4[i] = X4[i];
    __syncthreads();

    int tx = tid & 31;
    int ty = tid >> 5;
    float acc[8][4];
#pragma unroll
    for (int i = 0; i < 8; i++)
#pragma unroll
        for (int j = 0; j < 4; j++) acc[i][j] = 0.f;

    for (int k = 0; k < 64; k++) {
        float4 wv = *(const float4*)&Ws[k * 128 + tx * 4];
#pragma unroll
        for (int nn = 0; nn < 8; nn++) {
            float xv = Xs[(ty * 8 + nn) * 64 + k];
            acc[nn][0] += xv * wv.x;
            acc[nn][1] += xv * wv.y;
            acc[nn][2] += xv * wv.z;
            acc[nn][3] += xv * wv.w;
        }
    }
#pragma unroll
    for (int nn = 0; nn < 8; nn++) {
        int node = r0 + ty * 8 + nn;
        float di = g_dinv[node];
        float4 o = make_float4(acc[nn][0] * di, acc[nn][1] * di,
                               acc[nn][2] * di, acc[nn][3] * di);
        *(float4*)&g_bufA[(long long)node * 128 + tx * 4] = o;
    }
}

// ---------------- gather layer 1 ----------------
__global__ void k_gather128(const float* __restrict__ b1, int n) {
    int w = (blockIdx.x * blockDim.x + threadIdx.x) >> 5;
    int lane = threadIdx.x & 31;
    if (w >= n) return;
    int c = lane * 4;
    float4 acc = *(const float4*)&g_bufA[(long long)w * 128 + c];
    int e0 = g_rowptr[w], e1 = g_rowptr[w + 1];
    for (int e = e0; e < e1; e++) {
        int s = g_csr[e];
        float4 v = *(const float4*)&g_bufA[(long long)s * 128 + c];
        acc.x += v.x; acc.y += v.y; acc.z += v.z; acc.w += v.w;
    }
    float di = g_dinv[w];
    float4 bb = *(const float4*)&b1[c];
    float4 o = make_float4(fmaxf(di * acc.x + bb.x, 0.f),
                           fmaxf(di * acc.y + bb.y, 0.f),
                           fmaxf(di * acc.z + bb.z, 0.f),
                           fmaxf(di * acc.w + bb.w, 0.f));
    *(float4*)&g_bufB[(long long)w * 128 + c] = o;
}

// ---------------- GEMM2 ----------------
__global__ __launch_bounds__(256) void k_gemm2(const float* __restrict__ W2) {
    __shared__ float Xs[32 * 128];
    __shared__ float Ws[128 * 64];
    int tid = threadIdx.x;
    int r0 = blockIdx.x * 32;

    const float4* W4 = (const float4*)W2;
    float4* Ws4 = (float4*)Ws;
    for (int i = tid; i < 128 * 64 / 4; i += 256) Ws4[i] = W4[i];
    const float4* X4 = (const float4*)(g_bufB + (long long)r0 * 128);
    float4* Xs4 = (float4*)Xs;
    for (int i = tid; i < 32 * 128 / 4; i += 256) Xs4[i] = X4[i];
    __syncthreads();

    int tx = tid & 15;
    int ty = tid >> 4;
    float acc[2][4];
#pragma unroll
    for (int i = 0; i < 2; i++)
#pragma unroll
        for (int j = 0; j < 4; j++) acc[i][j] = 0.f;

    for (int k = 0; k < 128; k++) {
        float4 wv = *(const float4*)&Ws[k * 64 + tx * 4];
#pragma unroll
        for (int nn = 0; nn < 2; nn++) {
            float xv = Xs[(ty * 2 + nn) * 128 + k];
            acc[nn][0] += xv * wv.x;
            acc[nn][1] += xv * wv.y;
            acc[nn][2] += xv * wv.z;
            acc[nn][3] += xv * wv.w;
        }
    }
#pragma unroll
    for (int nn = 0; nn < 2; nn++) {
        int node = r0 + ty * 2 + nn;
        float di = g_dinv[node];
        float4 o = make_float4(acc[nn][0] * di, acc[nn][1] * di,
                               acc[nn][2] * di, acc[nn][3] * di);
        *(float4*)&g_bufA[(long long)node * 64 + tx * 4] = o;
    }
}

// ---------------- gather layer 2 -> half output (feeds only FC) ----------
__global__ void k_gather64(const float* __restrict__ b2, int n) {
    int w = (blockIdx.x * blockDim.x + threadIdx.x) >> 5;
    int lane = threadIdx.x & 31;
    if (w >= n) return;
    int c = lane * 2;
    float2 acc = *(const float2*)&g_bufA[(long long)w * 64 + c];
    int e0 = g_rowptr[w], e1 = g_rowptr[w + 1];
    for (int e = e0; e < e1; e++) {
        int s = g_csr[e];
        float2 v = *(const float2*)&g_bufA[(long long)s * 64 + c];
        acc.x += v.x; acc.y += v.y;
    }
    float di = g_dinv[w];
    float2 bb = *(const float2*)&b2[c];
    float ox = fmaxf(di * acc.x + bb.x, 0.f);
    float oy = fmaxf(di * acc.y + bb.y, 0.f);
    *(__half2*)&g_bufH[(long long)w * 64 + c] = __floats2half2_rn(ox, oy);
}

// ---------------- FC fp16: out = bufH[M,1920] @ Wfc + bfc ----------------
// tile 128x128, 256 thr, 8 warps (32x64 warp tiles), BK=32 halfs, double buffered.
#define LDA2 20   // words (half2) per A row: 16 + 4 pad

__global__ __launch_bounds__(256, 2) void k_fc_h(const float* __restrict__ bias,
                                                 float* __restrict__ C,
                                                 int M, int N, int K) {
    __shared__ unsigned As[2][128 * LDA2];   // [m][kp], word = half2
    __shared__ unsigned Bs[2][16 * 128];     // [kp][n ^ ((kp&3)<<3)]

    int tid = threadIdx.x;
    int m0 = blockIdx.y * 128;
    int bx = blockIdx.x;                     // n-block
    int n0 = bx * 128;

    int w    = tid >> 5;
    int wm   = (w >> 1) * 32;
    int wn   = (w & 1) * 64;
    int lane = tid & 31;
    int g = lane >> 2;
    int t = lane & 3;

    // copy coords
    int a_row  = tid >> 1;          // 0..127
    int a_part = tid & 1;           // 0..1  (16 halfs each)
    int b_ut0  = tid;               // uint4 index 0..255 (+256)

    float c[2][8][4];
#pragma unroll
    for (int i = 0; i < 2; i++)
#pragma unroll
        for (int j = 0; j < 8; j++)
#pragma unroll
            for (int q = 0; q < 4; q++) c[i][j][q] = 0.f;

    const __half* A = g_bufH;
    const __half* Bbase = g_Whalf + (long long)bx * (960 * 256);  // halfs

    int NKT = K / 32;   // 60

    // ---- prologue: tile 0 ----
    {
        const uint4* asrc = (const uint4*)(A + (long long)(m0 + a_row) * K + a_part * 16);
        uint4 u0 = asrc[0];
        int ad = a_row * LDA2 + a_part * 8;
        *(uint4*)&As[0][ad] = u0;
        const uint4* asrc2 = asrc + 1;
        uint4 u1 = asrc2[0];
        *(uint4*)&As[0][ad + 4] = u1;
#pragma unroll
        for (int it = 0; it < 2; it++) {
            int ut = b_ut0 + it * 256;
            int kp = ut >> 5;
            int ncol = (ut & 31) * 4;
            uint4 v = *(const uint4*)(Bbase + (long long)kp * 256 + ncol * 2);
            int dst = kp * 128 + (ncol ^ ((kp & 3) << 3));
            *(uint4*)&Bs[0][dst] = v;
        }
    }
    __syncthreads();

    for (int kt = 0; kt < NKT; kt++) {
        int cur = kt & 1;
        bool hn = (kt + 1) < NKT;
        uint4 ra0, ra1, rb0, rb1;
        if (hn) {
            int k0 = (kt + 1) * 32;
            const uint4* asrc = (const uint4*)(A + (long long)(m0 + a_row) * K + k0 + a_part * 16);
            ra0 = asrc[0];
            ra1 = asrc[1];
            int k0h = (kt + 1) * 16;
            {
                int ut = b_ut0;
                int kp = ut >> 5;
                int ncol = (ut & 31) * 4;
                rb0 = *(const uint4*)(Bbase + (long long)(k0h + kp) * 256 + ncol * 2);
                ut = b_ut0 + 256;
                kp = ut >> 5;
                ncol = (ut & 31) * 4;
                rb1 = *(const uint4*)(Bbase + (long long)(k0h + kp) * 256 + ncol * 2);
            }
        }

        const unsigned* as = As[cur];
        const unsigned* bs = Bs[cur];
#pragma unroll
        for (int ks = 0; ks < 2; ks++) {
            unsigned af[2][4];
#pragma unroll
            for (int i = 0; i < 2; i++) {
                int row = wm + 16 * i + g;
                int kp0 = 8 * ks + t;
                af[i][0] = as[row * LDA2 + kp0];
                af[i][1] = as[(row + 8) * LDA2 + kp0];
                af[i][2] = as[row * LDA2 + kp0 + 4];
                af[i][3] = as[(row + 8) * LDA2 + kp0 + 4];
            }
            unsigned bf[8][2];
#pragma unroll
            for (int j = 0; j < 8; j++) {
                int nn = (wn + 8 * j + g) ^ (t << 3);
                bf[j][0] = bs[(8 * ks + t) * 128 + nn];
                bf[j][1] = bs[(8 * ks + 4 + t) * 128 + nn];
            }
#pragma unroll
            for (int i = 0; i < 2; i++)
#pragma unroll
                for (int j = 0; j < 8; j++) {
                    asm volatile(
                        "mma.sync.aligned.m16n8k16.row.col.f32.f16.f16.f32 "
                        "{%0,%1,%2,%3}, {%4,%5,%6,%7}, {%8,%9}, {%0,%1,%2,%3};"
                        : "+f"(c[i][j][0]), "+f"(c[i][j][1]),
                          "+f"(c[i][j][2]), "+f"(c[i][j][3])
                        : "r"(af[i][0]), "r"(af[i][1]), "r"(af[i][2]), "r"(af[i][3]),
                          "r"(bf[j][0]), "r"(bf[j][1]));
                }
        }

        if (hn) {
            int nxt = (kt + 1) & 1;
            int ad = a_row * LDA2 + a_part * 8;
            *(uint4*)&As[nxt][ad] = ra0;
            *(uint4*)&As[nxt][ad + 4] = ra1;
            {
                int ut = b_ut0;
                int kp = ut >> 5;
                int ncol = (ut & 31) * 4;
                *(uint4*)&Bs[nxt][kp * 128 + (ncol ^ ((kp & 3) << 3))] = rb0;
                ut = b_ut0 + 256;
                kp = ut >> 5;
                ncol = (ut & 31) * 4;
                *(uint4*)&Bs[nxt][kp * 128 + (ncol ^ ((kp & 3) << 3))] = rb1;
            }
        }
        __syncthreads();
    }

    // ---- epilogue ----
#pragma unroll
    for (int i = 0; i < 2; i++) {
        int r0 = m0 + wm + 16 * i + g;
#pragma unroll
        for (int j = 0; j < 8; j++) {
            int cb = n0 + wn + 8 * j + 2 * t;
            if (cb < N) {
                float2 bb = *(const float2*)&bias[cb];
                float2 o0 = make_float2(c[i][j][0] + bb.x, c[i][j][1] + bb.y);
                float2 o1 = make_float2(c[i][j][2] + bb.x, c[i][j][3] + bb.y);
                *(float2*)&C[(long long)r0 * N + cb] = o0;
                *(float2*)&C[(long long)(r0 + 8) * N + cb] = o1;
            }
        }
    }
}

// ---------------- launch ----------------
extern "C" void kernel_launch(void* const* d_in, const int* in_sizes, int n_in,
                              void* d_out, int out_size) {
    const float* x   = (const float*)d_in[0];
    const int*   ei  = (const int*)d_in[1];
    const float* W1  = (const float*)d_in[2];
    const float* b1  = (const float*)d_in[3];
    const float* W2  = (const float*)d_in[4];
    const float* b2  = (const float*)d_in[5];
    const float* Wfc = (const float*)d_in[6];
    const float* bfc = (const float*)d_in[7];
    float* out = (float*)d_out;

    int n = in_sizes[0] / 64;     // 122880
    int E = in_sizes[1] / 2;      // 983040
    int M = out_size / 1728;      // 4096
    int Nfc = 1728, Kfc = 1920;

    k_zero_deg<<<(n + 255) / 256, 256>>>(n);
    k_detect<<<16, 256>>>(ei, 4096);
    k_count<<<(E + 255) / 256, 256>>>(ei, E, n);
    k_dinv<<<(n + 255) / 256, 256>>>(n);
    int nb = (n + 1023) / 1024;
    k_scan1<<<nb, 1024>>>(n);
    k_scan2<<<1, 1024>>>(nb);
    k_scan3<<<nb, 1024>>>(n, E);
    k_fill<<<(E + 255) / 256, 256>>>(ei, E, n);

    int wtot = 14 * 960 * 128;
    k_cvt_wh<<<(wtot + 255) / 256, 256>>>(Wfc, Nfc);

    k_gemm1<<<n / 64, 256>>>(x, W1);
    k_gather128<<<(n * 32 + 255) / 256, 256>>>(b1, n);
    k_gemm2<<<n / 32, 256>>>(W2);
    k_gather64<<<(n * 32 + 255) / 256, 256>>>(b2, n);

    dim3 g(14, M / 128);
    k_fc_h<<<g, 256>>>(bfc, out, M, Nfc, Kfc);
}

// round 6
// speedup vs baseline: 4.3062x; 1.5502x over previous
#include <cuda_runtime.h>
#include <cuda_fp16.h>

// ---------------- static scratch (no allocations allowed) ----------------
#define NMAX 122880
#define EMAX 983040

__device__ float g_dinv[NMAX];
__device__ int   g_deg[NMAX];
__device__ int   g_rowptr[NMAX + 1];
__device__ int   g_cursor[NMAX];
__device__ int   g_csr[EMAX];
__device__ int   g_bsum[256];
__device__ int   g_bsumx[256];
__device__ int   g_is64;

__device__ __half g_xh[NMAX * 64];     // dinv * x, half
__device__ __half g_agg1[NMAX * 64];   // (S+I) @ g_xh
__device__ __half g_y1[NMAX * 128];    // relu(dinv*(agg1@W1)+b1)
__device__ __half g_g2[NMAX * 64];     // dinv*(y1@W2)
__device__ __half g_bufH[NMAX * 64];   // FC A operand
__device__ __half g_W1h[32 * 128 * 2];      // W1 k-pair packed half2 [kp][n]
__device__ __half g_W2h[64 * 64 * 2];       // W2 k-pair packed
__device__ __half g_Whalf[14 * 960 * 256];  // Wfc blocked [nblk][kp][128 half2]

// ---------------- dtype detection ----------------
__global__ void k_detect(const int* __restrict__ w, int nwords) {
    int i = blockIdx.x * blockDim.x + threadIdx.x;
    if (i < nwords && (i & 1) && w[i] != 0) g_is64 = 0;
}

__global__ void k_zero_deg(int n) {
    int i = blockIdx.x * blockDim.x + threadIdx.x;
    if (i < n) g_deg[i] = 0;
    if (i == 0) g_is64 = 1;
}

__device__ __forceinline__ int load_idx(const int* w, long long pos) {
    return g_is64 ? w[2 * pos] : w[(int)pos];
}

__global__ void k_count(const int* __restrict__ w, int E, int n) {
    int e = blockIdx.x * blockDim.x + threadIdx.x;
    if (e < E) {
        int d = load_idx(w, (long long)E + e);
        d = min(max(d, 0), n - 1);
        atomicAdd(&g_deg[d], 1);
    }
}

__global__ void k_dinv(int n) {
    int i = blockIdx.x * blockDim.x + threadIdx.x;
    if (i < n) g_dinv[i] = rsqrtf((float)(g_deg[i] + 1));
}

// ---------------- exclusive scan ----------------
__global__ void k_scan1(int n) {
    __shared__ int sh[1024];
    int gid = blockIdx.x * 1024 + threadIdx.x;
    int v = (gid < n) ? g_deg[gid] : 0;
    sh[threadIdx.x] = v;
    __syncthreads();
    for (int off = 1; off < 1024; off <<= 1) {
        int t = (threadIdx.x >= off) ? sh[threadIdx.x - off] : 0;
        __syncthreads();
        sh[threadIdx.x] += t;
        __syncthreads();
    }
    if (gid < n) g_rowptr[gid] = sh[threadIdx.x] - v;
    if (threadIdx.x == 1023) g_bsum[blockIdx.x] = sh[1023];
}

__global__ void k_scan2(int nb) {
    __shared__ int sh[1024];
    int v = (threadIdx.x < nb) ? g_bsum[threadIdx.x] : 0;
    sh[threadIdx.x] = v;
    __syncthreads();
    for (int off = 1; off < 1024; off <<= 1) {
        int t = (threadIdx.x >= off) ? sh[threadIdx.x - off] : 0;
        __syncthreads();
        sh[threadIdx.x] += t;
        __syncthreads();
    }
    if (threadIdx.x < nb) g_bsumx[threadIdx.x] = sh[threadIdx.x] - v;
}

__global__ void k_scan3(int n, int E) {
    int gid = blockIdx.x * 1024 + threadIdx.x;
    if (gid < n) {
        int r = g_rowptr[gid] + g_bsumx[blockIdx.x];
        g_rowptr[gid] = r;
        g_cursor[gid] = r;
    }
    if (gid == 0) g_rowptr[n] = E;
}

__global__ void k_fill(const int* __restrict__ w, int E, int n) {
    int e = blockIdx.x * blockDim.x + threadIdx.x;
    if (e < E) {
        int d = load_idx(w, (long long)E + e);
        int s = load_idx(w, e);
        d = min(max(d, 0), n - 1);
        s = min(max(s, 0), n - 1);
        int slot = atomicAdd(&g_cursor[d], 1);
        g_csr[min(slot, EMAX - 1)] = s;
    }
}

// ---------------- weight conversions ----------------
__global__ void k_cvt_w1(const float* __restrict__ W) {  // [64,128] -> [32 kp][128]
    int idx = blockIdx.x * blockDim.x + threadIdx.x;
    if (idx >= 32 * 128) return;
    int n = idx & 127, kp = idx >> 7;
    ((__half2*)g_W1h)[idx] = __floats2half2_rn(W[(2 * kp) * 128 + n], W[(2 * kp + 1) * 128 + n]);
}

__global__ void k_cvt_w2(const float* __restrict__ W) {  // [128,64] -> [64 kp][64]
    int idx = blockIdx.x * blockDim.x + threadIdx.x;
    if (idx >= 64 * 64) return;
    int n = idx & 63, kp = idx >> 6;
    ((__half2*)g_W2h)[idx] = __floats2half2_rn(W[(2 * kp) * 64 + n], W[(2 * kp + 1) * 64 + n]);
}

__global__ void k_cvt_wh(const float* __restrict__ W, int N) {
    int idx = blockIdx.x * blockDim.x + threadIdx.x;
    if (idx >= 14 * 960 * 128) return;
    int n_local = idx & 127;
    int kp = (idx >> 7) % 960;
    int bx = idx / (960 * 128);
    int n = bx * 128 + n_local;
    float lo = 0.f, hi = 0.f;
    if (n < N) {
        lo = W[(long long)(2 * kp) * N + n];
        hi = W[(long long)(2 * kp + 1) * N + n];
    }
    ((__half2*)g_Whalf)[idx] = __floats2half2_rn(lo, hi);
}

// ---------------- xh = half(dinv * x) ----------------
__global__ void k_scale_x(const float* __restrict__ x, int n) {
    int idx = blockIdx.x * blockDim.x + threadIdx.x;  // half2 word
    if (idx >= n * 32) return;
    int node = idx >> 5;
    float2 v = ((const float2*)x)[idx];
    float di = g_dinv[node];
    ((__half2*)g_xh)[idx] = __floats2half2_rn(v.x * di, v.y * di);
}

// ---------------- gather 64-wide: dst = src[v] + sum_{s in in(v)} src[s] ------
__global__ void k_gather_in(int n) {
    int w = (blockIdx.x * blockDim.x + threadIdx.x) >> 5;
    int lane = threadIdx.x & 31;
    if (w >= n) return;
    const __half2* src = (const __half2*)g_xh;
    float2 acc = __half22float2(src[w * 32 + lane]);
    int e0 = g_rowptr[w], e1 = g_rowptr[w + 1];
    for (int e = e0; e < e1; e++) {
        int s = g_csr[e];
        float2 v = __half22float2(src[s * 32 + lane]);
        acc.x += v.x; acc.y += v.y;
    }
    ((__half2*)g_agg1)[w * 32 + lane] = __floats2half2_rn(acc.x, acc.y);
}

// ---------------- gather 64-wide out: bufH = relu(dinv*(g2[v]+sum)+b2) -------
__global__ void k_gather_out(const float* __restrict__ b2, int n) {
    int w = (blockIdx.x * blockDim.x + threadIdx.x) >> 5;
    int lane = threadIdx.x & 31;
    if (w >= n) return;
    const __half2* src = (const __half2*)g_g2;
    float2 acc = __half22float2(src[w * 32 + lane]);
    int e0 = g_rowptr[w], e1 = g_rowptr[w + 1];
    for (int e = e0; e < e1; e++) {
        int s = g_csr[e];
        float2 v = __half22float2(src[s * 32 + lane]);
        acc.x += v.x; acc.y += v.y;
    }
    float di = g_dinv[w];
    float2 bb = *(const float2*)&b2[lane * 2];
    float ox = fmaxf(di * acc.x + bb.x, 0.f);
    float oy = fmaxf(di * acc.y + bb.y, 0.f);
    ((__half2*)g_bufH)[w * 32 + lane] = __floats2half2_rn(ox, oy);
}

// ---------------- GEMM1 fp16: y1 = relu(dinv*(agg1 @ W1) + b1) ----------------
// M-tile 128 nodes, N=128, K=64. 8 warps, warp tile 32x64.
#define G1_LDA 36   // half2 words per A row (32 + 4 pad)

__global__ __launch_bounds__(256) void k_gemm1h(const float* __restrict__ b1, int n) {
    __shared__ unsigned As[128 * G1_LDA];
    __shared__ unsigned Bs[32 * 128];
    int tid = threadIdx.x;
    int r0 = blockIdx.x * 128;

    int w = tid >> 5, lane = tid & 31;
    int wm = (w >> 1) * 32, wn = (w & 1) * 64;
    int g = lane >> 2, t = lane & 3;

    // load A: 128 rows x 8 uint4
#pragma unroll
    for (int k = 0; k < 4; k++) {
        int ut = tid + k * 256;
        int row = ut >> 3, q = ut & 7;
        uint4 v = ((const uint4*)(g_agg1 + (long long)(r0 + row) * 64))[q];
        *(uint4*)&As[row * G1_LDA + q * 4] = v;
    }
    // load B: 32 kp x 128 n half2 = 1024 uint4, swizzled
#pragma unroll
    for (int k = 0; k < 4; k++) {
        int ut = tid + k * 256;
        int kp = ut >> 5, nc = (ut & 31) * 4;
        uint4 v = ((const uint4*)g_W1h)[ut];
        *(uint4*)&Bs[kp * 128 + (nc ^ ((kp & 3) << 3))] = v;
    }
    __syncthreads();

    float c[2][8][4];
#pragma unroll
    for (int i = 0; i < 2; i++)
#pragma unroll
        for (int j = 0; j < 8; j++)
#pragma unroll
            for (int q = 0; q < 4; q++) c[i][j][q] = 0.f;

#pragma unroll
    for (int ks = 0; ks < 4; ks++) {
        unsigned af[2][4];
#pragma unroll
        for (int i = 0; i < 2; i++) {
            int row = wm + 16 * i + g;
            int kp0 = 8 * ks + t;
            af[i][0] = As[row * G1_LDA + kp0];
            af[i][1] = As[(row + 8) * G1_LDA + kp0];
            af[i][2] = As[row * G1_LDA + kp0 + 4];
            af[i][3] = As[(row + 8) * G1_LDA + kp0 + 4];
        }
        unsigned bf[8][2];
#pragma unroll
        for (int j = 0; j < 8; j++) {
            int nn = (wn + 8 * j + g) ^ (t << 3);
            bf[j][0] = Bs[(8 * ks + t) * 128 + nn];
            bf[j][1] = Bs[(8 * ks + 4 + t) * 128 + nn];
        }
#pragma unroll
        for (int i = 0; i < 2; i++)
#pragma unroll
            for (int j = 0; j < 8; j++) {
                asm volatile(
                    "mma.sync.aligned.m16n8k16.row.col.f32.f16.f16.f32 "
                    "{%0,%1,%2,%3}, {%4,%5,%6,%7}, {%8,%9}, {%0,%1,%2,%3};"
                    : "+f"(c[i][j][0]), "+f"(c[i][j][1]),
                      "+f"(c[i][j][2]), "+f"(c[i][j][3])
                    : "r"(af[i][0]), "r"(af[i][1]), "r"(af[i][2]), "r"(af[i][3]),
                      "r"(bf[j][0]), "r"(bf[j][1]));
            }
    }

    // epilogue: relu(dinv*acc + b1) -> half2
#pragma unroll
    for (int i = 0; i < 2; i++) {
        int row = wm + 16 * i + g;
#pragma unroll
        for (int j = 0; j < 8; j++) {
            int col = wn + 8 * j + 2 * t;
            float2 bb = *(const float2*)&b1[col];
            int node0 = r0 + row;
            int node1 = node0 + 8;
            float d0 = g_dinv[node0], d1 = g_dinv[node1];
            ((__half2*)g_y1)[(long long)node0 * 64 + col / 2] =
                __floats2half2_rn(fmaxf(d0 * c[i][j][0] + bb.x, 0.f),
                                  fmaxf(d0 * c[i][j][1] + bb.y, 0.f));
            ((__half2*)g_y1)[(long long)node1 * 64 + col / 2] =
                __floats2half2_rn(fmaxf(d1 * c[i][j][2] + bb.x, 0.f),
                                  fmaxf(d1 * c[i][j][3] + bb.y, 0.f));
        }
    }
}

// ---------------- GEMM2 fp16: g2 = dinv*(y1 @ W2) -----------------------------
// M-tile 64 nodes, N=64, K=128. 8 warps, warp tile 16x32.
#define G2_LDA 68   // half2 words per A row (64 + 4 pad)

__global__ __launch_bounds__(256) void k_gemm2h(int n) {
    __shared__ unsigned As[64 * G2_LDA];
    __shared__ unsigned Bs[64 * 64];
    int tid = threadIdx.x;
    int r0 = blockIdx.x * 64;

    int w = tid >> 5, lane = tid & 31;
    int wm = (w >> 1) * 16, wn = (w & 1) * 32;
    int g = lane >> 2, t = lane & 3;

    // load A: 64 rows x 16 uint4 (128 halfs/row)
#pragma unroll
    for (int k = 0; k < 4; k++) {
        int ut = tid + k * 256;
        int row = ut >> 4, q = ut & 15;
        uint4 v = ((const uint4*)(g_y1 + (long long)(r0 + row) * 128))[q];
        *(uint4*)&As[row * G2_LDA + q * 4] = v;
    }
    // load B: 64 kp x 64 n half2 = 1024 uint4
#pragma unroll
    for (int k = 0; k < 4; k++) {
        int ut = tid + k * 256;
        int kp = ut >> 4, nc = (ut & 15) * 4;
        uint4 v = ((const uint4*)g_W2h)[ut];
        *(uint4*)&Bs[kp * 64 + (nc ^ ((kp & 3) << 3))] = v;
    }
    __syncthreads();

    float c[4][4];
#pragma unroll
    for (int j = 0; j < 4; j++)
#pragma unroll
        for (int q = 0; q < 4; q++) c[j][q] = 0.f;

#pragma unroll
    for (int ks = 0; ks < 8; ks++) {
        unsigned af[4];
        {
            int row = wm + g;
            int kp0 = 8 * ks + t;
            af[0] = As[row * G2_LDA + kp0];
            af[1] = As[(row + 8) * G2_LDA + kp0];
            af[2] = As[row * G2_LDA + kp0 + 4];
            af[3] = As[(row + 8) * G2_LDA + kp0 + 4];
        }
        unsigned bf[4][2];
#pragma unroll
        for (int j = 0; j < 4; j++) {
            int nn = (wn + 8 * j + g) ^ (t << 3);
            bf[j][0] = Bs[(8 * ks + t) * 64 + nn];
            bf[j][1] = Bs[(8 * ks + 4 + t) * 64 + nn];
        }
#pragma unroll
        for (int j = 0; j < 4; j++) {
            asm volatile(
                "mma.sync.aligned.m16n8k16.row.col.f32.f16.f16.f32 "
                "{%0,%1,%2,%3}, {%4,%5,%6,%7}, {%8,%9}, {%0,%1,%2,%3};"
                : "+f"(c[j][0]), "+f"(c[j][1]), "+f"(c[j][2]), "+f"(c[j][3])
                : "r"(af[0]), "r"(af[1]), "r"(af[2]), "r"(af[3]),
                  "r"(bf[j][0]), "r"(bf[j][1]));
        }
    }

    // epilogue: dinv*acc -> half2 (bias/relu applied after gather)
    {
        int row = wm + g;
        int node0 = r0 + row, node1 = node0 + 8;
        float d0 = g_dinv[node0], d1 = g_dinv[node1];
#pragma unroll
        for (int j = 0; j < 4; j++) {
            int col = wn + 8 * j + 2 * t;
            ((__half2*)g_g2)[(long long)node0 * 32 + col / 2] =
                __floats2half2_rn(d0 * c[j][0], d0 * c[j][1]);
            ((__half2*)g_g2)[(long long)node1 * 32 + col / 2] =
                __floats2half2_rn(d1 * c[j][2], d1 * c[j][3]);
        }
    }
}

// ---------------- FC fp16 (unchanged from R5) ----------------
#define LDA2 20

__global__ __launch_bounds__(256, 2) void k_fc_h(const float* __restrict__ bias,
                                                 float* __restrict__ C,
                                                 int M, int N, int K) {
    __shared__ unsigned As[2][128 * LDA2];
    __shared__ unsigned Bs[2][16 * 128];

    int tid = threadIdx.x;
    int m0 = blockIdx.y * 128;
    int bx = blockIdx.x;
    int n0 = bx * 128;

    int w = tid >> 5;
    int wm = (w >> 1) * 32;
    int wn = (w & 1) * 64;
    int lane = tid & 31;
    int g = lane >> 2;
    int t = lane & 3;

    int a_row = tid >> 1;
    int a_part = tid & 1;
    int b_ut0 = tid;

    float c[2][8][4];
#pragma unroll
    for (int i = 0; i < 2; i++)
#pragma unroll
        for (int j = 0; j < 8; j++)
#pragma unroll
            for (int q = 0; q < 4; q++) c[i][j][q] = 0.f;

    const __half* A = g_bufH;
    const __half* Bbase = g_Whalf + (long long)bx * (960 * 256);

    int NKT = K / 32;

    {
        const uint4* asrc = (const uint4*)(A + (long long)(m0 + a_row) * K + a_part * 16);
        uint4 u0 = asrc[0];
        int ad = a_row * LDA2 + a_part * 8;
        *(uint4*)&As[0][ad] = u0;
        uint4 u1 = asrc[1];
        *(uint4*)&As[0][ad + 4] = u1;
#pragma unroll
        for (int it = 0; it < 2; it++) {
            int ut = b_ut0 + it * 256;
            int kp = ut >> 5;
            int ncol = (ut & 31) * 4;
            uint4 v = *(const uint4*)(Bbase + (long long)kp * 256 + ncol * 2);
            *(uint4*)&Bs[0][kp * 128 + (ncol ^ ((kp & 3) << 3))] = v;
        }
    }
    __syncthreads();

    for (int kt = 0; kt < NKT; kt++) {
        int cur = kt & 1;
        bool hn = (kt + 1) < NKT;
        uint4 ra0, ra1, rb0, rb1;
        if (hn) {
            int k0 = (kt + 1) * 32;
            const uint4* asrc = (const uint4*)(A + (long long)(m0 + a_row) * K + k0 + a_part * 16);
            ra0 = asrc[0];
            ra1 = asrc[1];
            int k0h = (kt + 1) * 16;
            int ut = b_ut0;
            int kp = ut >> 5;
            int ncol = (ut & 31) * 4;
            rb0 = *(const uint4*)(Bbase + (long long)(k0h + kp) * 256 + ncol * 2);
            ut = b_ut0 + 256;
            kp = ut >> 5;
            ncol = (ut & 31) * 4;
            rb1 = *(const uint4*)(Bbase + (long long)(k0h + kp) * 256 + ncol * 2);
        }

        const unsigned* as = As[cur];
        const unsigned* bs = Bs[cur];
#pragma unroll
        for (int ks = 0; ks < 2; ks++) {
            unsigned af[2][4];
#pragma unroll
            for (int i = 0; i < 2; i++) {
                int row = wm + 16 * i + g;
                int kp0 = 8 * ks + t;
                af[i][0] = as[row * LDA2 + kp0];
                af[i][1] = as[(row + 8) * LDA2 + kp0];
                af[i][2] = as[row * LDA2 + kp0 + 4];
                af[i][3] = as[(row + 8) * LDA2 + kp0 + 4];
            }
            unsigned bf[8][2];
#pragma unroll
            for (int j = 0; j < 8; j++) {
                int nn = (wn + 8 * j + g) ^ (t << 3);
                bf[j][0] = bs[(8 * ks + t) * 128 + nn];
                bf[j][1] = bs[(8 * ks + 4 + t) * 128 + nn];
            }
#pragma unroll
            for (int i = 0; i < 2; i++)
#pragma unroll
                for (int j = 0; j < 8; j++) {
                    asm volatile(
                        "mma.sync.aligned.m16n8k16.row.col.f32.f16.f16.f32 "
                        "{%0,%1,%2,%3}, {%4,%5,%6,%7}, {%8,%9}, {%0,%1,%2,%3};"
                        : "+f"(c[i][j][0]), "+f"(c[i][j][1]),
                          "+f"(c[i][j][2]), "+f"(c[i][j][3])
                        : "r"(af[i][0]), "r"(af[i][1]), "r"(af[i][2]), "r"(af[i][3]),
                          "r"(bf[j][0]), "r"(bf[j][1]));
                }
        }

        if (hn) {
            int nxt = (kt + 1) & 1;
            int ad = a_row * LDA2 + a_part * 8;
            *(uint4*)&As[nxt][ad] = ra0;
            *(uint4*)&As[nxt][ad + 4] = ra1;
            int ut = b_ut0;
            int kp = ut >> 5;
            int ncol = (ut & 31) * 4;
            *(uint4*)&Bs[nxt][kp * 128 + (ncol ^ ((kp & 3) << 3))] = rb0;
            ut = b_ut0 + 256;
            kp = ut >> 5;
            ncol = (ut & 31) * 4;
            *(uint4*)&Bs[nxt][kp * 128 + (ncol ^ ((kp & 3) << 3))] = rb1;
        }
        __syncthreads();
    }

#pragma unroll
    for (int i = 0; i < 2; i++) {
        int r0 = m0 + wm + 16 * i + g;
#pragma unroll
        for (int j = 0; j < 8; j++) {
            int cb = n0 + wn + 8 * j + 2 * t;
            if (cb < N) {
                float2 bb = *(const float2*)&bias[cb];
                float2 o0 = make_float2(c[i][j][0] + bb.x, c[i][j][1] + bb.y);
                float2 o1 = make_float2(c[i][j][2] + bb.x, c[i][j][3] + bb.y);
                *(float2*)&C[(long long)r0 * N + cb] = o0;
                *(float2*)&C[(long long)(r0 + 8) * N + cb] = o1;
            }
        }
    }
}

// ---------------- launch ----------------
extern "C" void kernel_launch(void* const* d_in, const int* in_sizes, int n_in,
                              void* d_out, int out_size) {
    const float* x   = (const float*)d_in[0];
    const int*   ei  = (const int*)d_in[1];
    const float* W1  = (const float*)d_in[2];
    const float* b1  = (const float*)d_in[3];
    const float* W2  = (const float*)d_in[4];
    const float* b2  = (const float*)d_in[5];
    const float* Wfc = (const float*)d_in[6];
    const float* bfc = (const float*)d_in[7];
    float* out = (float*)d_out;

    int n = in_sizes[0] / 64;     // 122880
    int E = in_sizes[1] / 2;      // 983040
    int M = out_size / 1728;      // 4096
    int Nfc = 1728, Kfc = 1920;

    // graph structure
    k_zero_deg<<<(n + 255) / 256, 256>>>(n);
    k_detect<<<16, 256>>>(ei, 4096);
    k_count<<<(E + 255) / 256, 256>>>(ei, E, n);
    k_dinv<<<(n + 255) / 256, 256>>>(n);
    int nb = (n + 1023) / 1024;
    k_scan1<<<nb, 1024>>>(n);
    k_scan2<<<1, 1024>>>(nb);
    k_scan3<<<nb, 1024>>>(n, E);
    k_fill<<<(E + 255) / 256, 256>>>(ei, E, n);

    // weight conversions
    k_cvt_w1<<<16, 256>>>(W1);
    k_cvt_w2<<<16, 256>>>(W2);
    int wtot = 14 * 960 * 128;
    k_cvt_wh<<<(wtot + 255) / 256, 256>>>(Wfc, Nfc);

    // layer 1: scale -> gather(64) -> GEMM(64->128) w/ relu
    k_scale_x<<<(n * 32 + 255) / 256, 256>>>(x, n);
    k_gather_in<<<(n * 32 + 255) / 256, 256>>>(n);
    k_gemm1h<<<n / 128, 256>>>(b1, n);

    // layer 2: GEMM(128->64) -> gather(64) w/ bias+relu
    k_gemm2h<<<n / 64, 256>>>(n);
    k_gather_out<<<(n * 32 + 255) / 256, 256>>>(b2, n);

    // FC head
    dim3 g(14, M / 128);
    k_fc_h<<<g, 256>>>(bfc, out, M, Nfc, Kfc);
}

// round 9
// speedup vs baseline: 4.4642x; 1.0367x over previous
#include <cuda_runtime.h>
#include <cuda_fp16.h>
#include <cstdint>

// ---------------- static scratch (no allocations allowed) ----------------
#define NMAX 122880
#define EMAX 983040

__device__ float g_dinv[NMAX];
__device__ int   g_deg[NMAX];
__device__ int   g_rowptr[NMAX + 1];
__device__ int   g_cursor[NMAX];
__device__ int   g_csr[EMAX];
__device__ int   g_bsum[256];
__device__ int   g_bsumx[256];
__device__ int   g_is64;

__device__ __half g_xh[NMAX * 64];
__device__ __half g_agg1[NMAX * 64];
__device__ __half g_y1[NMAX * 128];
__device__ __half g_g2[NMAX * 64];
__device__ __half g_bufH[NMAX * 64];            // FC A operand [4096][1920]
__device__ __half g_W1h[32 * 128 * 2];
__device__ __half g_W2h[64 * 64 * 2];
// Wfc^T for FC: [14 nblk][30 kchunk][128 n][32 kp] half2 linear
__device__ __half g_Wt[14 * 30 * 8192];

// ---------------- dtype detection ----------------
__global__ void k_detect(const int* __restrict__ w, int nwords) {
    int i = blockIdx.x * blockDim.x + threadIdx.x;
    if (i < nwords && (i & 1) && w[i] != 0) g_is64 = 0;
}

__global__ void k_zero_deg(int n) {
    int i = blockIdx.x * blockDim.x + threadIdx.x;
    if (i < n) g_deg[i] = 0;
    if (i == 0) g_is64 = 1;
}

__device__ __forceinline__ int load_idx(const int* w, long long pos) {
    return g_is64 ? w[2 * pos] : w[(int)pos];
}

__global__ void k_count(const int* __restrict__ w, int E, int n) {
    int e = blockIdx.x * blockDim.x + threadIdx.x;
    if (e < E) {
        int d = load_idx(w, (long long)E + e);
        d = min(max(d, 0), n - 1);
        atomicAdd(&g_deg[d], 1);
    }
}

// ---------------- exclusive scan (scan1 also computes dinv) ----------------
__global__ void k_scan1(int n) {
    __shared__ int sh[1024];
    int gid = blockIdx.x * 1024 + threadIdx.x;
    int v = (gid < n) ? g_deg[gid] : 0;
    sh[threadIdx.x] = v;
    __syncthreads();
    for (int off = 1; off < 1024; off <<= 1) {
        int t = (threadIdx.x >= off) ? sh[threadIdx.x - off] : 0;
        __syncthreads();
        sh[threadIdx.x] += t;
        __syncthreads();
    }
    if (gid < n) {
        g_rowptr[gid] = sh[threadIdx.x] - v;
        g_dinv[gid] = rsqrtf((float)(v + 1));
    }
    if (threadIdx.x == 1023) g_bsum[blockIdx.x] = sh[1023];
}

__global__ void k_scan2(int nb) {
    __shared__ int sh[1024];
    int v = (threadIdx.x < nb) ? g_bsum[threadIdx.x] : 0;
    sh[threadIdx.x] = v;
    __syncthreads();
    for (int off = 1; off < 1024; off <<= 1) {
        int t = (threadIdx.x >= off) ? sh[threadIdx.x - off] : 0;
        __syncthreads();
        sh[threadIdx.x] += t;
        __syncthreads();
    }
    if (threadIdx.x < nb) g_bsumx[threadIdx.x] = sh[threadIdx.x] - v;
}

__global__ void k_scan3(int n, int E) {
    int gid = blockIdx.x * 1024 + threadIdx.x;
    if (gid < n) {
        int r = g_rowptr[gid] + g_bsumx[blockIdx.x];
        g_rowptr[gid] = r;
        g_cursor[gid] = r;
    }
    if (gid == 0) g_rowptr[n] = E;
}

__global__ void k_fill(const int* __restrict__ w, int E, int n) {
    int e = blockIdx.x * blockDim.x + threadIdx.x;
    if (e < E) {
        int d = load_idx(w, (long long)E + e);
        int s = load_idx(w, e);
        d = min(max(d, 0), n - 1);
        s = min(max(s, 0), n - 1);
        int slot = atomicAdd(&g_cursor[d], 1);
        g_csr[min(slot, EMAX - 1)] = s;
    }
}

// ---------------- all weight conversions in one kernel ----------------
__global__ void k_cvt_all(const float* __restrict__ W1, const float* __restrict__ W2,
                          const float* __restrict__ Wfc, int N) {
    int idx = blockIdx.x * blockDim.x + threadIdx.x;
    if (idx < 4096) {
        int n = idx & 127, kp = idx >> 7;
        ((__half2*)g_W1h)[idx] =
            __floats2half2_rn(W1[(2 * kp) * 128 + n], W1[(2 * kp + 1) * 128 + n]);
    } else if (idx < 8192) {
        int j = idx - 4096;
        int n = j & 63, kp = j >> 6;
        ((__half2*)g_W2h)[j] =
            __floats2half2_rn(W2[(2 * kp) * 64 + n], W2[(2 * kp + 1) * 64 + n]);
    } else {
        int j = idx - 8192;
        if (j < 14 * 30 * 4096) {
            int kp = j & 31;
            int n  = (j >> 5) & 127;
            int c  = (j >> 12) % 30;
            int nb = j / 122880;           // 30*4096
            int gn = nb * 128 + n;
            int gk = c * 64 + 2 * kp;
            float lo = 0.f, hi = 0.f;
            if (gn < N) {
                lo = Wfc[(long long)gk * N + gn];
                hi = Wfc[(long long)(gk + 1) * N + gn];
            }
            ((__half2*)g_Wt)[j] = __floats2half2_rn(lo, hi);
        }
    }
}

// ---------------- xh = half(dinv * x) ----------------
__global__ void k_scale_x(const float* __restrict__ x, int n) {
    int idx = blockIdx.x * blockDim.x + threadIdx.x;
    if (idx >= n * 32) return;
    int node = idx >> 5;
    float2 v = ((const float2*)x)[idx];
    float di = g_dinv[node];
    ((__half2*)g_xh)[idx] = __floats2half2_rn(v.x * di, v.y * di);
}

// ---------------- gathers (edge loop unrolled x4) ----------------
__global__ void k_gather_in(int n) {
    int w = (blockIdx.x * blockDim.x + threadIdx.x) >> 5;
    int lane = threadIdx.x & 31;
    if (w >= n) return;
    const __half2* src = (const __half2*)g_xh;
    float2 acc = __half22float2(src[w * 32 + lane]);
    int e0 = g_rowptr[w], e1 = g_rowptr[w + 1];
    int e = e0;
    for (; e + 4 <= e1; e += 4) {
        int s0 = g_csr[e], s1 = g_csr[e + 1], s2 = g_csr[e + 2], s3 = g_csr[e + 3];
        float2 v0 = __half22float2(src[s0 * 32 + lane]);
        float2 v1 = __half22float2(src[s1 * 32 + lane]);
        float2 v2 = __half22float2(src[s2 * 32 + lane]);
        float2 v3 = __half22float2(src[s3 * 32 + lane]);
        acc.x += (v0.x + v1.x) + (v2.x + v3.x);
        acc.y += (v0.y + v1.y) + (v2.y + v3.y);
    }
    for (; e < e1; e++) {
        float2 v = __half22float2(src[g_csr[e] * 32 + lane]);
        acc.x += v.x; acc.y += v.y;
    }
    ((__half2*)g_agg1)[w * 32 + lane] = __floats2half2_rn(acc.x, acc.y);
}

__global__ void k_gather_out(const float* __restrict__ b2, int n) {
    int w = (blockIdx.x * blockDim.x + threadIdx.x) >> 5;
    int lane = threadIdx.x & 31;
    if (w >= n) return;
    const __half2* src = (const __half2*)g_g2;
    float2 acc = __half22float2(src[w * 32 + lane]);
    int e0 = g_rowptr[w], e1 = g_rowptr[w + 1];
    int e = e0;
    for (; e + 4 <= e1; e += 4) {
        int s0 = g_csr[e], s1 = g_csr[e + 1], s2 = g_csr[e + 2], s3 = g_csr[e + 3];
        float2 v0 = __half22float2(src[s0 * 32 + lane]);
        float2 v1 = __half22float2(src[s1 * 32 + lane]);
        float2 v2 = __half22float2(src[s2 * 32 + lane]);
        float2 v3 = __half22float2(src[s3 * 32 + lane]);
        acc.x += (v0.x + v1.x) + (v2.x + v3.x);
        acc.y += (v0.y + v1.y) + (v2.y + v3.y);
    }
    for (; e < e1; e++) {
        float2 v = __half22float2(src[g_csr[e] * 32 + lane]);
        acc.x += v.x; acc.y += v.y;
    }
    float di = g_dinv[w];
    float2 bb = *(const float2*)&b2[lane * 2];
    float ox = fmaxf(di * acc.x + bb.x, 0.f);
    float oy = fmaxf(di * acc.y + bb.y, 0.f);
    ((__half2*)g_bufH)[w * 32 + lane] = __floats2half2_rn(ox, oy);
}

// ---------------- GEMM1 fp16 (mma.sync) ----------------
#define G1_LDA 36

__global__ __launch_bounds__(256) void k_gemm1h(const float* __restrict__ b1, int n) {
    __shared__ unsigned As[128 * G1_LDA];
    __shared__ unsigned Bs[32 * 128];
    int tid = threadIdx.x;
    int r0 = blockIdx.x * 128;

    int w = tid >> 5, lane = tid & 31;
    int wm = (w >> 1) * 32, wn = (w & 1) * 64;
    int g = lane >> 2, t = lane & 3;

#pragma unroll
    for (int k = 0; k < 4; k++) {
        int ut = tid + k * 256;
        int row = ut >> 3, q = ut & 7;
        uint4 v = ((const uint4*)(g_agg1 + (long long)(r0 + row) * 64))[q];
        *(uint4*)&As[row * G1_LDA + q * 4] = v;
    }
#pragma unroll
    for (int k = 0; k < 4; k++) {
        int ut = tid + k * 256;
        int kp = ut >> 5, nc = (ut & 31) * 4;
        uint4 v = ((const uint4*)g_W1h)[ut];
        *(uint4*)&Bs[kp * 128 + (nc ^ ((kp & 3) << 3))] = v;
    }
    __syncthreads();

    float c[2][8][4];
#pragma unroll
    for (int i = 0; i < 2; i++)
#pragma unroll
        for (int j = 0; j < 8; j++)
#pragma unroll
            for (int q = 0; q < 4; q++) c[i][j][q] = 0.f;

#pragma unroll
    for (int ks = 0; ks < 4; ks++) {
        unsigned af[2][4];
#pragma unroll
        for (int i = 0; i < 2; i++) {
            int row = wm + 16 * i + g;
            int kp0 = 8 * ks + t;
            af[i][0] = As[row * G1_LDA + kp0];
            af[i][1] = As[(row + 8) * G1_LDA + kp0];
            af[i][2] = As[row * G1_LDA + kp0 + 4];
            af[i][3] = As[(row + 8) * G1_LDA + kp0 + 4];
        }
        unsigned bf[8][2];
#pragma unroll
        for (int j = 0; j < 8; j++) {
            int nn = (wn + 8 * j + g) ^ (t << 3);
            bf[j][0] = Bs[(8 * ks + t) * 128 + nn];
            bf[j][1] = Bs[(8 * ks + 4 + t) * 128 + nn];
        }
#pragma unroll
        for (int i = 0; i < 2; i++)
#pragma unroll
            for (int j = 0; j < 8; j++) {
                asm volatile(
                    "mma.sync.aligned.m16n8k16.row.col.f32.f16.f16.f32 "
                    "{%0,%1,%2,%3}, {%4,%5,%6,%7}, {%8,%9}, {%0,%1,%2,%3};"
                    : "+f"(c[i][j][0]), "+f"(c[i][j][1]),
                      "+f"(c[i][j][2]), "+f"(c[i][j][3])
                    : "r"(af[i][0]), "r"(af[i][1]), "r"(af[i][2]), "r"(af[i][3]),
                      "r"(bf[j][0]), "r"(bf[j][1]));
            }
    }

#pragma unroll
    for (int i = 0; i < 2; i++) {
        int row = wm + 16 * i + g;
#pragma unroll
        for (int j = 0; j < 8; j++) {
            int col = wn + 8 * j + 2 * t;
            float2 bb = *(const float2*)&b1[col];
            int node0 = r0 + row;
            int node1 = node0 + 8;
            float d0 = g_dinv[node0], d1 = g_dinv[node1];
            ((__half2*)g_y1)[(long long)node0 * 64 + col / 2] =
                __floats2half2_rn(fmaxf(d0 * c[i][j][0] + bb.x, 0.f),
                                  fmaxf(d0 * c[i][j][1] + bb.y, 0.f));
            ((__half2*)g_y1)[(long long)node1 * 64 + col / 2] =
                __floats2half2_rn(fmaxf(d1 * c[i][j][2] + bb.x, 0.f),
                                  fmaxf(d1 * c[i][j][3] + bb.y, 0.f));
        }
    }
}

// ---------------- GEMM2 fp16 (mma.sync) ----------------
#define G2_LDA 68

__global__ __launch_bounds__(256) void k_gemm2h(int n) {
    __shared__ unsigned As[64 * G2_LDA];
    __shared__ unsigned Bs[64 * 64];
    int tid = threadIdx.x;
    int r0 = blockIdx.x * 64;

    int w = tid >> 5, lane = tid & 31;
    int wm = (w >> 1) * 16, wn = (w & 1) * 32;
    int g = lane >> 2, t = lane & 3;

#pragma unroll
    for (int k = 0; k < 4; k++) {
        int ut = tid + k * 256;
        int row = ut >> 4, q = ut & 15;
        uint4 v = ((const uint4*)(g_y1 + (long long)(r0 + row) * 128))[q];
        *(uint4*)&As[row * G2_LDA + q * 4] = v;
    }
#pragma unroll
    for (int k = 0; k < 4; k++) {
        int ut = tid + k * 256;
        int kp = ut >> 4, nc = (ut & 15) * 4;
        uint4 v = ((const uint4*)g_W2h)[ut];
        *(uint4*)&Bs[kp * 64 + (nc ^ ((kp & 3) << 3))] = v;
    }
    __syncthreads();

    float c[4][4];
#pragma unroll
    for (int j = 0; j < 4; j++)
#pragma unroll
        for (int q = 0; q < 4; q++) c[j][q] = 0.f;

#pragma unroll
    for (int ks = 0; ks < 8; ks++) {
        unsigned af[4];
        {
            int row = wm + g;
            int kp0 = 8 * ks + t;
            af[0] = As[row * G2_LDA + kp0];
            af[1] = As[(row + 8) * G2_LDA + kp0];
            af[2] = As[row * G2_LDA + kp0 + 4];
            af[3] = As[(row + 8) * G2_LDA + kp0 + 4];
        }
        unsigned bf[4][2];
#pragma unroll
        for (int j = 0; j < 4; j++) {
            int nn = (wn + 8 * j + g) ^ (t << 3);
            bf[j][0] = Bs[(8 * ks + t) * 64 + nn];
            bf[j][1] = Bs[(8 * ks + 4 + t) * 64 + nn];
        }
#pragma unroll
        for (int j = 0; j < 4; j++) {
            asm volatile(
                "mma.sync.aligned.m16n8k16.row.col.f32.f16.f16.f32 "
                "{%0,%1,%2,%3}, {%4,%5,%6,%7}, {%8,%9}, {%0,%1,%2,%3};"
                : "+f"(c[j][0]), "+f"(c[j][1]), "+f"(c[j][2]), "+f"(c[j][3])
                : "r"(af[0]), "r"(af[1]), "r"(af[2]), "r"(af[3]),
                  "r"(bf[j][0]), "r"(bf[j][1]));
        }
    }

    {
        int row = wm + g;
        int node0 = r0 + row, node1 = node0 + 8;
        float d0 = g_dinv[node0], d1 = g_dinv[node1];
#pragma unroll
        for (int j = 0; j < 4; j++) {
            int col = wn + 8 * j + 2 * t;
            ((__half2*)g_g2)[(long long)node0 * 32 + col / 2] =
                __floats2half2_rn(d0 * c[j][0], d0 * c[j][1]);
            ((__half2*)g_g2)[(long long)node1 * 32 + col / 2] =
                __floats2half2_rn(d1 * c[j][2], d1 * c[j][3]);
        }
    }
}

// ---------------- FC fp16 mma.sync, ldmatrix fragments ----------------
// Block tile 128x128, 512 thr / 16 warps, warp tile 32x32, BK=64, double buffered.
// smem: [512:1024) bias, stages at 1024; stage = A(128x36w) + B(128x36w) = 36864 B.
#define FC_STG 36864

__device__ __forceinline__ uint32_t smem_u32(const void* p) {
    uint32_t a;
    asm("{ .reg .u64 t; cvta.to.shared.u64 t, %1; cvt.u32.u64 %0, t; }" : "=r"(a) : "l"(p));
    return a;
}

__global__ __launch_bounds__(512) void k_fc2(const float* __restrict__ bias,
                                             float* __restrict__ out,
                                             int M, int N, int K) {
    extern __shared__ char sm[];
    uint32_t sb = smem_u32(sm);
    int tid = threadIdx.x, wid = tid >> 5, lane = tid & 31;
    int m0 = blockIdx.y * 128;
    int bx = blockIdx.x, n0 = bx * 128;
    int wm = (wid >> 2) * 32, wn = (wid & 3) * 32;
    int g = lane >> 2, t = lane & 3;
    int lrow = lane & 15, lcolw = (lane >> 4) * 4;

    if (tid < 128) {
        int gn = n0 + tid;
        *(float*)(sm + 512 + tid * 4) = (gn < N) ? bias[gn] : 0.f;
    }

    const __half* A = g_bufH;
    const __half2* Bt = (const __half2*)g_Wt + (long long)(bx * 30) * 4096;

    float c[2][4][4];
#pragma unroll
    for (int i = 0; i < 2; i++)
#pragma unroll
        for (int j = 0; j < 4; j++)
#pragma unroll
            for (int q = 0; q < 4; q++) c[i][j][q] = 0.f;

    // prologue: chunk 0 -> stage 0
#pragma unroll
    for (int i = 0; i < 2; i++) {
        int ut = tid + i * 512;
        int r = ut >> 3, q = ut & 7;
        uint4 va = ((const uint4*)(A + (long long)(m0 + r) * K))[q];
        *(uint4*)(sm + 1024 + (r * 36 + q * 4) * 4) = va;
        uint4 vb = ((const uint4*)Bt)[ut];
        *(uint4*)(sm + 1024 + 18432 + (r * 36 + q * 4) * 4) = vb;
    }
    __syncthreads();

    for (int ch = 0; ch < 30; ch++) {
        int cur = ch & 1;
        bool hn = (ch + 1) < 30;
        uint4 ra[2], rb[2];
        if (hn) {
            int kc = (ch + 1) * 64;
#pragma unroll
            for (int i = 0; i < 2; i++) {
                int ut = tid + i * 512;
                int r = ut >> 3, q = ut & 7;
                ra[i] = ((const uint4*)(A + (long long)(m0 + r) * K + kc))[q];
                rb[i] = ((const uint4*)(Bt + (long long)(ch + 1) * 4096))[ut];
            }
        }

        uint32_t sA = sb + 1024 + cur * FC_STG;
        uint32_t sB = sA + 18432;
#pragma unroll
        for (int ks = 0; ks < 4; ks++) {
            int kw = ks * 8 + lcolw;
            unsigned af[2][4], bf[4][2];
#pragma unroll
            for (int i = 0; i < 2; i++) {
                uint32_t ad = sA + (uint32_t)(((wm + 16 * i + lrow) * 36 + kw) * 4);
                asm volatile(
                    "ldmatrix.sync.aligned.m8n8.x4.shared.b16 {%0,%1,%2,%3}, [%4];"
                    : "=r"(af[i][0]), "=r"(af[i][1]), "=r"(af[i][2]), "=r"(af[i][3])
                    : "r"(ad));
            }
#pragma unroll
            for (int jb = 0; jb < 2; jb++) {
                unsigned q0, q1, q2, q3;
                uint32_t bd = sB + (uint32_t)(((wn + 16 * jb + lrow) * 36 + kw) * 4);
                asm volatile(
                    "ldmatrix.sync.aligned.m8n8.x4.shared.b16 {%0,%1,%2,%3}, [%4];"
                    : "=r"(q0), "=r"(q1), "=r"(q2), "=r"(q3)
                    : "r"(bd));
                bf[2 * jb][0] = q0; bf[2 * jb + 1][0] = q1;
                bf[2 * jb][1] = q2; bf[2 * jb + 1][1] = q3;
            }
#pragma unroll
            for (int i = 0; i < 2; i++)
#pragma unroll
                for (int j = 0; j < 4; j++) {
                    asm volatile(
                        "mma.sync.aligned.m16n8k16.row.col.f32.f16.f16.f32 "
                        "{%0,%1,%2,%3}, {%4,%5,%6,%7}, {%8,%9}, {%0,%1,%2,%3};"
                        : "+f"(c[i][j][0]), "+f"(c[i][j][1]),
                          "+f"(c[i][j][2]), "+f"(c[i][j][3])
                        : "r"(af[i][0]), "r"(af[i][1]), "r"(af[i][2]), "r"(af[i][3]),
                          "r"(bf[j][0]), "r"(bf[j][1]));
                }
        }

        if (hn) {
            char* dA = sm + 1024 + ((ch + 1) & 1) * FC_STG;
#pragma unroll
            for (int i = 0; i < 2; i++) {
                int ut = tid + i * 512;
                int r = ut >> 3, q = ut & 7;
                *(uint4*)(dA + (r * 36 + q * 4) * 4) = ra[i];
                *(uint4*)(dA + 18432 + (r * 36 + q * 4) * 4) = rb[i];
            }
        }
        __syncthreads();
    }

    // epilogue
    const float* bs = (const float*)(sm + 512);
#pragma unroll
    for (int i = 0; i < 2; i++) {
        int row = m0 + wm + 16 * i + g;
#pragma unroll
        for (int j = 0; j < 4; j++) {
            int lb = wn + 8 * j + 2 * t;
            int cb = n0 + lb;
            if (cb < N) {
                float2 bb = make_float2(bs[lb], bs[lb + 1]);
                float2 o0 = make_float2(c[i][j][0] + bb.x, c[i][j][1] + bb.y);
                float2 o1 = make_float2(c[i][j][2] + bb.x, c[i][j][3] + bb.y);
                *(float2*)&out[(long long)row * N + cb] = o0;
                *(float2*)&out[(long long)(row + 8) * N + cb] = o1;
            }
        }
    }
}

// ---------------- launch ----------------
extern "C" void kernel_launch(void* const* d_in, const int* in_sizes, int n_in,
                              void* d_out, int out_size) {
    const float* x   = (const float*)d_in[0];
    const int*   ei  = (const int*)d_in[1];
    const float* W1  = (const float*)d_in[2];
    const float* b1  = (const float*)d_in[3];
    const float* W2  = (const float*)d_in[4];
    const float* b2  = (const float*)d_in[5];
    const float* Wfc = (const float*)d_in[6];
    const float* bfc = (const float*)d_in[7];
    float* out = (float*)d_out;

    int n = in_sizes[0] / 64;     // 122880
    int E = in_sizes[1] / 2;      // 983040
    int M = out_size / 1728;      // 4096
    int Nfc = 1728, Kfc = 1920;

    // graph structure
    k_zero_deg<<<(n + 255) / 256, 256>>>(n);
    k_detect<<<16, 256>>>(ei, 4096);
    k_count<<<(E + 255) / 256, 256>>>(ei, E, n);
    int nb = (n + 1023) / 1024;
    k_scan1<<<nb, 1024>>>(n);
    k_scan2<<<1, 1024>>>(nb);
    k_scan3<<<nb, 1024>>>(n, E);
    k_fill<<<(E + 255) / 256, 256>>>(ei, E, n);

    // weights (single kernel)
    int cvt_tot = 8192 + 14 * 30 * 4096;
    k_cvt_all<<<(cvt_tot + 255) / 256, 256>>>(W1, W2, Wfc, Nfc);

    // node pipeline
    k_scale_x<<<(n * 32 + 255) / 256, 256>>>(x, n);
    k_gather_in<<<(n * 32 + 255) / 256, 256>>>(n);
    k_gemm1h<<<n / 128, 256>>>(b1, n);
    k_gemm2h<<<n / 64, 256>>>(n);
    k_gather_out<<<(n * 32 + 255) / 256, 256>>>(b2, n);

    // FC head
    static int fc_attr_set = 0;
    if (!fc_attr_set) {
        cudaFuncSetAttribute(k_fc2, cudaFuncAttributeMaxDynamicSharedMemorySize,
                             1024 + 2 * FC_STG);
        fc_attr_set = 1;
    }
    dim3 g(14, M / 128);
    k_fc2<<<g, 512, 1024 + 2 * FC_STG>>>(bfc, out, M, Nfc, Kfc);
}